// round 3
// baseline (speedup 1.0000x reference)
#include <cuda_runtime.h>
#include <math.h>

#define BB   256
#define NPIX 1089
#define MDIM 272
#define CC   32
#define PADS 36
#define CH_STRIDE (35*PADS)   /* 1260 floats per padded channel */
#define CONV_THREADS 384

#define FLAG_ACT_IN 1
#define FLAG_FLIP   2
#define FLAG_ACTDER 4
#define FLAG_GNORM  8

typedef unsigned long long u64;

// ---------------- device state (static, no allocation) ----------------
__device__ float d_P[NPIX*NPIX];
__device__ float d_PhiTb[BB*NPIX];
__device__ float d_x[BB*NPIX];
__device__ float d_z[BB*NPIX];
__device__ float d_gphi[BB*NPIX];
__device__ float d_dotm[BB*NPIX];
__device__ float d_x1[BB*CC*NPIX];
__device__ float d_x2[BB*CC*NPIX];
__device__ float d_x3[BB*CC*NPIX];
__device__ float d_g [BB*CC*NPIX];
__device__ float d_bA[BB*CC*NPIX];
__device__ float d_ngrad[BB];
__device__ float d_gamma;

// ---------------- packed f32x2 helpers ----------------
__device__ __forceinline__ u64 pk2(float a, float b) {
    u64 r; asm("mov.b64 %0, {%1,%2};" : "=l"(r) : "f"(a), "f"(b)); return r;
}
__device__ __forceinline__ void fma2(u64& d, u64 a, u64 b) {
    asm("fma.rn.f32x2 %0, %1, %2, %3;" : "=l"(d) : "l"(a), "l"(b), "l"(d));
}
__device__ __forceinline__ float2 upk2(u64 v) {
    float2 f; asm("mov.b64 {%0,%1}, %2;" : "=f"(f.x), "=f"(f.y) : "l"(v)); return f;
}

// ---------------- activation (eq. 33), DELTA = 0.01 ----------------
__device__ __forceinline__ float actf(float v) {
    if (fabsf(v) > 0.01f) return fmaxf(v, 0.0f);
    return fmaf(v*v, 25.0f, fmaf(v, 0.5f, 0.0025f));
}
__device__ __forceinline__ float actdf(float v) {
    if (fabsf(v) > 0.01f) return v > 0.0f ? 1.0f : 0.0f;
    return fmaf(v, 50.0f, 0.5f);
}

// ---------------- GEMM: P = Phi^T Phi (64x64 tiles, 4x4 per thread) ----------------
__global__ void k_phitphi64(const float* __restrict__ Phi) {
    if (blockIdx.x == 0 && blockIdx.y == 0 && threadIdx.x == 0 && threadIdx.y == 0)
        d_gamma = 1.0f;
    __shared__ float As[16][68];
    __shared__ float Bs[16][68];
    int ib = blockIdx.y * 64, jb = blockIdx.x * 64;
    int tx = threadIdx.x, ty = threadIdx.y;
    int t = ty * 16 + tx;
    float acc[4][4];
    #pragma unroll
    for (int r = 0; r < 4; r++)
        #pragma unroll
        for (int c = 0; c < 4; c++) acc[r][c] = 0.f;

    for (int k0 = 0; k0 < MDIM; k0 += 16) {
        #pragma unroll
        for (int q = t; q < 1024; q += 256) {
            int kk = q / 64, r = q % 64;
            As[kk][r] = (ib + r < NPIX) ? Phi[(k0 + kk) * NPIX + ib + r] : 0.f;
            Bs[kk][r] = (jb + r < NPIX) ? Phi[(k0 + kk) * NPIX + jb + r] : 0.f;
        }
        __syncthreads();
        #pragma unroll
        for (int kk = 0; kk < 16; kk++) {
            float4 a4 = *(const float4*)&As[kk][ty * 4];
            float4 b4 = *(const float4*)&Bs[kk][tx * 4];
            float ar[4] = {a4.x, a4.y, a4.z, a4.w};
            float br[4] = {b4.x, b4.y, b4.z, b4.w};
            #pragma unroll
            for (int r = 0; r < 4; r++)
                #pragma unroll
                for (int c = 0; c < 4; c++)
                    acc[r][c] = fmaf(ar[r], br[c], acc[r][c]);
        }
        __syncthreads();
    }
    #pragma unroll
    for (int r = 0; r < 4; r++) {
        int i = ib + ty * 4 + r;
        if (i >= NPIX) continue;
        #pragma unroll
        for (int c = 0; c < 4; c++) {
            int j = jb + tx * 4 + c;
            if (j < NPIX) d_P[i * NPIX + j] = acc[r][c];
        }
    }
}

// ---------------- phase GEMM: dot = src @ P  (64x64, 4x4) ----------------
// mode 0 (Z):    dst = src + |alphas[p]|*(PhiTb - dot)
// mode 1 (DOTM): dst = dot - PhiTb
__global__ void k_gemmP(const float* __restrict__ src, float* __restrict__ dst,
                        const float* __restrict__ alphas, int phase, int mode) {
    __shared__ float As[16][68];
    __shared__ float Bs[16][68];
    int bb = blockIdx.y * 64, jb = blockIdx.x * 64;
    int tx = threadIdx.x, ty = threadIdx.y;
    int t = ty * 16 + tx;
    float acc[4][4];
    #pragma unroll
    for (int r = 0; r < 4; r++)
        #pragma unroll
        for (int c = 0; c < 4; c++) acc[r][c] = 0.f;

    for (int k0 = 0; k0 < NPIX; k0 += 16) {
        #pragma unroll
        for (int q = t; q < 1024; q += 256) {
            int r = q / 16, kk = q % 16;
            As[kk][r] = (k0 + kk < NPIX) ? src[(bb + r) * NPIX + k0 + kk] : 0.f;
        }
        #pragma unroll
        for (int q = t; q < 1024; q += 256) {
            int kk = q / 64, c = q % 64;
            Bs[kk][c] = (k0 + kk < NPIX && jb + c < NPIX) ? d_P[(k0 + kk) * NPIX + jb + c] : 0.f;
        }
        __syncthreads();
        #pragma unroll
        for (int kk = 0; kk < 16; kk++) {
            float4 a4 = *(const float4*)&As[kk][ty * 4];
            float4 b4 = *(const float4*)&Bs[kk][tx * 4];
            float ar[4] = {a4.x, a4.y, a4.z, a4.w};
            float br[4] = {b4.x, b4.y, b4.z, b4.w};
            #pragma unroll
            for (int r = 0; r < 4; r++)
                #pragma unroll
                for (int c = 0; c < 4; c++)
                    acc[r][c] = fmaf(ar[r], br[c], acc[r][c]);
        }
        __syncthreads();
    }
    float alpha = fabsf(alphas[phase]);
    #pragma unroll
    for (int r = 0; r < 4; r++) {
        int b = bb + ty * 4 + r;
        #pragma unroll
        for (int c = 0; c < 4; c++) {
            int j = jb + tx * 4 + c;
            if (j < NPIX) {
                float dot = acc[r][c];
                float ptb = d_PhiTb[b * NPIX + j];
                if (mode == 0)
                    dst[b * NPIX + j] = src[b * NPIX + j] + alpha * (ptb - dot);
                else
                    dst[b * NPIX + j] = dot - ptb;
            }
        }
    }
}

// ---------------- z step (reuse stored dotm): z = x - |alpha|*dotm ----------------
__global__ void k_zstep(const float* __restrict__ x, float* __restrict__ z,
                        const float* __restrict__ alphas, int phase) {
    float alpha = fabsf(alphas[phase]);
    size_t base = (size_t)blockIdx.x * NPIX;
    for (int j = threadIdx.x; j < NPIX; j += blockDim.x)
        z[base + j] = x[base + j] - alpha * d_dotm[base + j];
}

// ---------------- fused setup GEMMs (blockIdx.z: 0 = PhiTb, 1 = x0) ----------------
__global__ void k_setupF(const float* __restrict__ Phix, const float* __restrict__ Phi,
                         const float* __restrict__ Qinit,
                         float* __restrict__ dPhiTb, float* __restrict__ dx) {
    __shared__ float As[32][33];
    __shared__ float Bs[32][33];
    int tmode = blockIdx.z;
    const float* Bsrc = tmode == 0 ? Phi : Qinit;
    float* dst = tmode == 0 ? dPhiTb : dx;
    int bb = blockIdx.y * 32, jb = blockIdx.x * 32;
    int tx = threadIdx.x, ty = threadIdx.y;
    int t = ty * 16 + tx;
    float acc00 = 0.f, acc01 = 0.f, acc10 = 0.f, acc11 = 0.f;
    for (int k0 = 0; k0 < MDIM; k0 += 32) {
        for (int q = t; q < 1024; q += 256) {
            int kk = q % 32, r = q / 32;
            As[kk][r] = (k0 + kk < MDIM) ? Phix[(bb + r) * MDIM + k0 + kk] : 0.f;
        }
        if (tmode == 0) {
            for (int q = t; q < 1024; q += 256) {
                int kk = q / 32, j = q % 32;
                Bs[kk][j] = (k0 + kk < MDIM && jb + j < NPIX) ? Bsrc[(k0 + kk) * NPIX + jb + j] : 0.f;
            }
        } else {
            for (int q = t; q < 1024; q += 256) {
                int kk = q % 32, j = q / 32;
                Bs[kk][j] = (k0 + kk < MDIM && jb + j < NPIX) ? Bsrc[(jb + j) * MDIM + k0 + kk] : 0.f;
            }
        }
        __syncthreads();
        #pragma unroll
        for (int kk = 0; kk < 32; kk++) {
            float a0 = As[kk][ty*2], a1 = As[kk][ty*2+1];
            float b0 = Bs[kk][tx*2], b1 = Bs[kk][tx*2+1];
            acc00 = fmaf(a0, b0, acc00); acc01 = fmaf(a0, b1, acc01);
            acc10 = fmaf(a1, b0, acc10); acc11 = fmaf(a1, b1, acc11);
        }
        __syncthreads();
    }
    int b0 = bb + ty*2, j0 = jb + tx*2;
    if (j0     < NPIX) dst[(b0  ) * NPIX + j0  ] = acc00;
    if (j0 + 1 < NPIX) dst[(b0  ) * NPIX + j0+1] = acc01;
    if (j0     < NPIX) dst[(b0+1) * NPIX + j0  ] = acc10;
    if (j0 + 1 < NPIX) dst[(b0+1) * NPIX + j0+1] = acc11;
}

// ---------------- heavy conv core: 1 pixel/thread, 16 f32x2 channel-pair accs ----------
__device__ __forceinline__ void conv_core(const float* s_in, const float* s_w,
                                          float* __restrict__ outb,
                                          const float* __restrict__ preb,
                                          bool actder, int tid) {
    for (int p = tid; p < NPIX; p += CONV_THREADS) {
        int y = p / 33, x = p - y * 33;
        u64 acc[16];
        #pragma unroll
        for (int i = 0; i < 16; i++) acc[i] = 0ull;
        const float* sb = s_in + y * PADS + x;
        for (int ci = 0; ci < CC; ci++) {
            const float* sp = sb + ci * CH_STRIDE;
            float rr[9];
            rr[0] = sp[0];        rr[1] = sp[1];        rr[2] = sp[2];
            rr[3] = sp[PADS];     rr[4] = sp[PADS+1];   rr[5] = sp[PADS+2];
            rr[6] = sp[2*PADS];   rr[7] = sp[2*PADS+1]; rr[8] = sp[2*PADS+2];
            const u64* wp = (const u64*)(s_w + ci * 9 * CC);
            #pragma unroll
            for (int k = 0; k < 9; k++) {
                u64 vp = pk2(rr[k], rr[k]);
                const ulonglong2* w2 = (const ulonglong2*)(wp + k * 16);
                #pragma unroll
                for (int j = 0; j < 8; j++) {
                    ulonglong2 ww = w2[j];            // LDS.128 broadcast
                    fma2(acc[2*j],   vp, ww.x);
                    fma2(acc[2*j+1], vp, ww.y);
                }
            }
        }
        #pragma unroll
        for (int cp = 0; cp < 16; cp++) {
            float2 a = upk2(acc[cp]);
            int co0 = 2*cp, co1 = 2*cp + 1;
            if (actder) {
                a.x *= actdf(preb[co0 * NPIX + p]);
                a.y *= actdf(preb[co1 * NPIX + p]);
            }
            outb[co0 * NPIX + p] = a.x;
            outb[co1 * NPIX + p] = a.y;
        }
    }
}

// stage weights into s_w with layout [ci][k][co] (optionally flipped/transposed)
__device__ __forceinline__ void stage_w(const float* __restrict__ w, float* s_w,
                                        bool flip, int tid) {
    for (int idx = tid; idx < CC * CC * 9; idx += CONV_THREADS) {
        int kx = idx % 3, ky = (idx / 3) % 3;
        int i = (idx / 9) % CC, o = idx / (9 * CC);
        float v = w[idx];
        int eci, eco, ek;
        if (flip) { eci = o; eco = i; ek = (2 - ky) * 3 + (2 - kx); }
        else      { eci = i; eco = o; ek = ky * 3 + kx; }
        s_w[(eci * 9 + ek) * CC + eco] = v;
    }
}

// ---------------- heavy 32->32 3x3 conv (fwd or transposed) ----------------
__global__ __launch_bounds__(CONV_THREADS, 1) void k_conv(
        const float* __restrict__ in, const float* __restrict__ w,
        float* __restrict__ out, const float* __restrict__ pre,
        const float* __restrict__ soft, int flags) {
    extern __shared__ float smem[];
    float* s_in = smem;                    // CC * CH_STRIDE
    float* s_w  = smem + CC * CH_STRIDE;   // [ci][k][co]
    int n = blockIdx.x, tid = threadIdx.x;

    for (int i = tid; i < CC * CH_STRIDE; i += CONV_THREADS) s_in[i] = 0.f;
    stage_w(w, s_w, (flags & FLAG_FLIP) != 0, tid);
    __syncthreads();

    const float* inb = in + (size_t)n * CC * NPIX;
    bool act_in = (flags & FLAG_ACT_IN) != 0;
    for (int idx = tid; idx < CC * NPIX; idx += CONV_THREADS) {
        int ci = idx / NPIX, p = idx - ci * NPIX;
        int y = p / 33, x = p - y * 33;
        float v = inb[idx];
        if (act_in) v = actf(v);
        s_in[ci * CH_STRIDE + (y + 1) * PADS + (x + 1)] = v;
    }
    __syncthreads();

    if (flags & FLAG_GNORM) {
        float thr = soft[0] * d_gamma;
        float inv_thr = 1.0f / thr;
        for (int p = tid; p < NPIX; p += CONV_THREADS) {
            int y = p / 33, x = p - y * 33;
            int off = (y + 1) * PADS + (x + 1);
            float v[CC];
            float s = 0.f;
            #pragma unroll
            for (int c = 0; c < CC; c++) {
                v[c] = s_in[c * CH_STRIDE + off];
                s = fmaf(v[c], v[c], s);
            }
            float nrm = sqrtf(s);
            float f = (nrm > thr) ? (1.0f / fmaxf(nrm, 1e-12f)) : inv_thr;
            #pragma unroll
            for (int c = 0; c < CC; c++) s_in[c * CH_STRIDE + off] = v[c] * f;
        }
        __syncthreads();
    }

    conv_core(s_in, s_w,
              out + (size_t)n * CC * NPIX,
              pre + (size_t)n * CC * NPIX,
              (flags & FLAG_ACTDER) != 0, tid);
}

// ---------------- fused conv1 + conv2: z -> x1 (gmem) -> act -> conv2 -> x2 ----------
__global__ __launch_bounds__(CONV_THREADS, 1) void k_conv12(
        const float* __restrict__ z, const float* __restrict__ w1,
        const float* __restrict__ w2,
        float* __restrict__ x1out, float* __restrict__ x2out) {
    extern __shared__ float smem[];
    float* s_in = smem;                           // CC * CH_STRIDE (act(x1), padded)
    float* s_w  = s_in + CC * CH_STRIDE;          // CC*CC*9 (c2 weights)
    float* s_z  = s_w + CC * CC * 9;              // CH_STRIDE (padded z)
    float* s_w1 = s_z + CH_STRIDE;                // 9*CC  [k][co]
    int n = blockIdx.x, tid = threadIdx.x;

    for (int i = tid; i < CC * CH_STRIDE; i += CONV_THREADS) s_in[i] = 0.f;
    for (int i = tid; i < CH_STRIDE; i += CONV_THREADS) s_z[i] = 0.f;
    stage_w(w2, s_w, false, tid);
    for (int idx = tid; idx < CC * 9; idx += CONV_THREADS) {
        int o = idx / 9, k = idx % 9;
        s_w1[k * CC + o] = w1[idx];
    }
    __syncthreads();

    const float* zb = z + (size_t)n * NPIX;
    for (int p = tid; p < NPIX; p += CONV_THREADS) {
        int y = p / 33, x = p - y * 33;
        s_z[(y + 1) * PADS + (x + 1)] = zb[p];
    }
    __syncthreads();

    // conv1: thread per pixel, all 32 output channels
    float* x1b = x1out + (size_t)n * CC * NPIX;
    for (int p = tid; p < NPIX; p += CONV_THREADS) {
        int y = p / 33, x = p - y * 33;
        const float* sp = s_z + y * PADS + x;
        float zv[9];
        zv[0]=sp[0]; zv[1]=sp[1]; zv[2]=sp[2];
        zv[3]=sp[PADS]; zv[4]=sp[PADS+1]; zv[5]=sp[PADS+2];
        zv[6]=sp[2*PADS]; zv[7]=sp[2*PADS+1]; zv[8]=sp[2*PADS+2];
        float acc[CC];
        #pragma unroll
        for (int co = 0; co < CC; co++) acc[co] = 0.f;
        #pragma unroll
        for (int k = 0; k < 9; k++) {
            #pragma unroll
            for (int c4 = 0; c4 < 8; c4++) {
                float4 wv = *(const float4*)(s_w1 + k * CC + c4 * 4);
                acc[c4*4+0] = fmaf(zv[k], wv.x, acc[c4*4+0]);
                acc[c4*4+1] = fmaf(zv[k], wv.y, acc[c4*4+1]);
                acc[c4*4+2] = fmaf(zv[k], wv.z, acc[c4*4+2]);
                acc[c4*4+3] = fmaf(zv[k], wv.w, acc[c4*4+3]);
            }
        }
        int off = (y + 1) * PADS + (x + 1);
        #pragma unroll
        for (int co = 0; co < CC; co++) {
            x1b[co * NPIX + p] = acc[co];
            s_in[co * CH_STRIDE + off] = actf(acc[co]);
        }
    }
    __syncthreads();

    conv_core(s_in, s_w, x2out + (size_t)n * CC * NPIX,
              x1out, false, tid);
}

// ---------------- convT1 (32 -> 1), fused with x/gphi update ----------------
__global__ __launch_bounds__(CONV_THREADS, 1) void k_convT1(
        const float* __restrict__ in, const float* __restrict__ w1,
        const float* __restrict__ z, float* __restrict__ x,
        const float* __restrict__ dotm, float* __restrict__ gphi,
        const float* __restrict__ alphas, const float* __restrict__ betas,
        int phase, int mode, float* __restrict__ out_extra) {
    extern __shared__ float smem[];
    float* s_in = smem;                 // CC * CH_STRIDE
    __shared__ float s_w[CC * 9];       // flipped [o][k]
    int n = blockIdx.x, tid = threadIdx.x;
    for (int i = tid; i < CC * CH_STRIDE; i += CONV_THREADS) s_in[i] = 0.f;
    for (int idx = tid; idx < CC * 9; idx += CONV_THREADS) {
        int o = idx / 9, k = idx % 9;
        int ky = k / 3, kx = k % 3;
        s_w[o * 9 + (2 - ky) * 3 + (2 - kx)] = w1[idx];
    }
    __syncthreads();
    const float* inb = in + (size_t)n * CC * NPIX;
    for (int idx = tid; idx < CC * NPIX; idx += CONV_THREADS) {
        int ci = idx / NPIX, p = idx - ci * NPIX;
        int y = p / 33, x2 = p - y * 33;
        s_in[ci * CH_STRIDE + (y + 1) * PADS + (x2 + 1)] = inb[idx];
    }
    __syncthreads();

    float a = fabsf(alphas[phase]), b = fabsf(betas[phase]);
    float tau = a * b / (a + b);

    for (int p = tid; p < NPIX; p += CONV_THREADS) {
        int y = p / 33, xx = p - y * 33;
        float acc = 0.f;
        const float* sbase = s_in + y * PADS + xx;
        for (int o = 0; o < CC; o++) {
            const float* sp = sbase + o * CH_STRIDE;
            const float* wp = s_w + o * 9;
            #pragma unroll
            for (int k = 0; k < 9; k++)
                acc = fmaf(sp[(k / 3) * PADS + (k % 3)], wp[k], acc);
        }
        size_t off = (size_t)n * NPIX + p;
        if (mode == 0) {
            float nx = z[off] - tau * acc;
            x[off] = nx;
            if (out_extra) out_extra[off] = nx;
        } else {
            gphi[off] = dotm[off] + acc;
        }
    }
}

// ---------------- row norms + gamma update ----------------
__global__ void k_rownorm(const float* __restrict__ gphi) {
    __shared__ float red[256];
    int bidx = blockIdx.x;
    float s = 0.f;
    for (int j = threadIdx.x; j < NPIX; j += 256) {
        float v = gphi[(size_t)bidx * NPIX + j];
        s = fmaf(v, v, s);
    }
    red[threadIdx.x] = s;
    __syncthreads();
    for (int off = 128; off > 0; off >>= 1) {
        if (threadIdx.x < off) red[threadIdx.x] += red[threadIdx.x + off];
        __syncthreads();
    }
    if (threadIdx.x == 0) d_ngrad[bidx] = sqrtf(red[0]);
}

__global__ void k_gamma(const float* __restrict__ soft_thr) {
    __shared__ float red[256];
    red[threadIdx.x] = d_ngrad[threadIdx.x];
    __syncthreads();
    for (int off = 128; off > 0; off >>= 1) {
        if (threadIdx.x < off) red[threadIdx.x] += red[threadIdx.x + off];
        __syncthreads();
    }
    if (threadIdx.x == 0) {
        float mean = red[0] / (float)BB;
        float g = d_gamma;
        if (mean < 15000.0f * g * soft_thr[0]) g *= 0.9f;
        d_gamma = g;
    }
}

// ---------------- host orchestration ----------------
#define SMEM_CONV ((CC * CH_STRIDE + CC * CC * 9) * (int)sizeof(float))              /* 198144 */
#define SMEM_C12  ((CC * CH_STRIDE + CC * CC * 9 + CH_STRIDE + 9 * CC) * (int)sizeof(float)) /* 204336 */
#define SMEM_T1   ((CC * CH_STRIDE) * (int)sizeof(float))                            /* 161280 */

static void grad_r_chain(const float* src, const float* c1, const float* c2,
                         const float* c3, const float* c4, const float* soft,
                         float* px1, float* px2, float* px3, float* pg, float* pbA,
                         const float* pz, float* px, const float* pdotm, float* pgphi,
                         const float* alphas, const float* betas,
                         int phase, int mode, float* out_extra) {
    k_conv12<<<BB, CONV_THREADS, SMEM_C12>>>(src, c1, c2, px1, px2);
    k_conv<<<BB, CONV_THREADS, SMEM_CONV>>>(px2, c3, px3, px1, soft, FLAG_ACT_IN);
    k_conv<<<BB, CONV_THREADS, SMEM_CONV>>>(px3, c4, pg,  px1, soft, FLAG_ACT_IN);
    k_conv<<<BB, CONV_THREADS, SMEM_CONV>>>(pg,  c4, pbA, px3, soft, FLAG_FLIP | FLAG_ACTDER | FLAG_GNORM);
    k_conv<<<BB, CONV_THREADS, SMEM_CONV>>>(pbA, c3, pg,  px2, soft, FLAG_FLIP | FLAG_ACTDER);
    k_conv<<<BB, CONV_THREADS, SMEM_CONV>>>(pg,  c2, pbA, px1, soft, FLAG_FLIP | FLAG_ACTDER);
    k_convT1<<<BB, CONV_THREADS, SMEM_T1>>>(pbA, c1, pz, px, pdotm, pgphi,
                                            alphas, betas, phase, mode, out_extra);
}

extern "C" void kernel_launch(void* const* d_in, const int* in_sizes, int n_in,
                              void* d_out, int out_size) {
    (void)in_sizes; (void)n_in; (void)out_size;
    const float* Phix   = (const float*)d_in[0];
    const float* Phi    = (const float*)d_in[1];
    const float* Qinit  = (const float*)d_in[2];
    const float* soft   = (const float*)d_in[3];
    const float* alphas = (const float*)d_in[4];
    const float* betas  = (const float*)d_in[5];
    const float* c1     = (const float*)d_in[6];
    const float* c2     = (const float*)d_in[7];
    const float* c3     = (const float*)d_in[8];
    const float* c4     = (const float*)d_in[9];
    float* out = (float*)d_out;

    cudaFuncSetAttribute(k_conv,   cudaFuncAttributeMaxDynamicSharedMemorySize, SMEM_CONV);
    cudaFuncSetAttribute(k_conv12, cudaFuncAttributeMaxDynamicSharedMemorySize, SMEM_C12);
    cudaFuncSetAttribute(k_convT1, cudaFuncAttributeMaxDynamicSharedMemorySize, SMEM_T1);

    float *px, *pz, *pgphi, *pdotm, *px1, *px2, *px3, *pg, *pbA, *pPhiTb;
    cudaGetSymbolAddress((void**)&px,     d_x);
    cudaGetSymbolAddress((void**)&pz,     d_z);
    cudaGetSymbolAddress((void**)&pgphi,  d_gphi);
    cudaGetSymbolAddress((void**)&pdotm,  d_dotm);
    cudaGetSymbolAddress((void**)&px1,    d_x1);
    cudaGetSymbolAddress((void**)&px2,    d_x2);
    cudaGetSymbolAddress((void**)&px3,    d_x3);
    cudaGetSymbolAddress((void**)&pg,     d_g);
    cudaGetSymbolAddress((void**)&pbA,    d_bA);
    cudaGetSymbolAddress((void**)&pPhiTb, d_PhiTb);

    dim3 tb16(16, 16);
    // launch order keeps the heavy k_conv12 as the 4th user launch (profiling target)
    k_phitphi64<<<dim3(18, 18), tb16>>>(Phi);                       // + gamma init
    k_setupF<<<dim3(35, 8, 2), tb16>>>(Phix, Phi, Qinit, pPhiTb, px);

    for (int p = 0; p < 3; p++) {
        if (p == 0)
            k_gemmP<<<dim3(18, 4), tb16>>>(px, pz, alphas, p, 0);
        else
            k_zstep<<<BB, 256>>>(px, pz, alphas, p);
        grad_r_chain(pz, c1, c2, c3, c4, soft, px1, px2, px3, pg, pbA,
                     pz, px, pdotm, pgphi, alphas, betas, p, 0,
                     (p == 2) ? out : nullptr);
        if (p < 2) {
            k_gemmP<<<dim3(18, 4), tb16>>>(px, pdotm, alphas, p, 1);
            grad_r_chain(px, c1, c2, c3, c4, soft, px1, px2, px3, pg, pbA,
                         pz, px, pdotm, pgphi, alphas, betas, p, 1, nullptr);
            k_rownorm<<<BB, 256>>>(pgphi);
            k_gamma<<<1, 256>>>(soft);
        }
    }
}

// round 4
// speedup vs baseline: 1.1590x; 1.1590x over previous
#include <cuda_runtime.h>
#include <math.h>

#define BB   256
#define NPIX 1089
#define MDIM 272
#define CC   32
#define PADS 36
#define CH_STRIDE (35*PADS)   /* 1260 floats per padded channel */
#define CONV_THREADS 384
#define NITEM 1092            /* 273 pixel-quads * 4 channel-groups */

#define FLAG_ACT_IN 1
#define FLAG_FLIP   2
#define FLAG_ACTDER 4
#define FLAG_GNORM  8

typedef unsigned long long u64;

// ---------------- device state (static, no allocation) ----------------
__device__ float d_P[NPIX*NPIX];
__device__ float d_PhiTb[BB*NPIX];
__device__ float d_x[BB*NPIX];
__device__ float d_z[BB*NPIX];
__device__ float d_gphi[BB*NPIX];
__device__ float d_dotm[BB*NPIX];
__device__ float d_x1[BB*CC*NPIX];
__device__ float d_x2[BB*CC*NPIX];
__device__ float d_x3[BB*CC*NPIX];
__device__ float d_g [BB*CC*NPIX];
__device__ float d_bA[BB*CC*NPIX];
__device__ float d_ngrad[BB];
__device__ float d_gamma;

// ---------------- packed f32x2 helpers ----------------
__device__ __forceinline__ u64 pk2(float a, float b) {
    u64 r; asm("mov.b64 %0, {%1,%2};" : "=l"(r) : "f"(a), "f"(b)); return r;
}
__device__ __forceinline__ void fma2(u64& d, u64 a, u64 b) {
    asm("fma.rn.f32x2 %0, %1, %2, %3;" : "=l"(d) : "l"(a), "l"(b), "l"(d));
}
__device__ __forceinline__ float2 upk2(u64 v) {
    float2 f; asm("mov.b64 {%0,%1}, %2;" : "=f"(f.x), "=f"(f.y) : "l"(v)); return f;
}

// ---------------- activation (eq. 33), DELTA = 0.01 ----------------
__device__ __forceinline__ float actf(float v) {
    if (fabsf(v) > 0.01f) return fmaxf(v, 0.0f);
    return fmaf(v*v, 25.0f, fmaf(v, 0.5f, 0.0025f));
}
__device__ __forceinline__ float actdf(float v) {
    if (fabsf(v) > 0.01f) return v > 0.0f ? 1.0f : 0.0f;
    return fmaf(v, 50.0f, 0.5f);
}

// ---------------- GEMM: P = Phi^T Phi (64x64 tiles, 4x4 per thread) ----------------
__global__ void k_phitphi64(const float* __restrict__ Phi) {
    if (blockIdx.x == 0 && blockIdx.y == 0 && threadIdx.x == 0 && threadIdx.y == 0)
        d_gamma = 1.0f;
    __shared__ float As[16][68];
    __shared__ float Bs[16][68];
    int ib = blockIdx.y * 64, jb = blockIdx.x * 64;
    int tx = threadIdx.x, ty = threadIdx.y;
    int t = ty * 16 + tx;
    float acc[4][4];
    #pragma unroll
    for (int r = 0; r < 4; r++)
        #pragma unroll
        for (int c = 0; c < 4; c++) acc[r][c] = 0.f;

    for (int k0 = 0; k0 < MDIM; k0 += 16) {
        #pragma unroll
        for (int q = t; q < 1024; q += 256) {
            int kk = q / 64, r = q % 64;
            As[kk][r] = (ib + r < NPIX) ? Phi[(k0 + kk) * NPIX + ib + r] : 0.f;
            Bs[kk][r] = (jb + r < NPIX) ? Phi[(k0 + kk) * NPIX + jb + r] : 0.f;
        }
        __syncthreads();
        #pragma unroll
        for (int kk = 0; kk < 16; kk++) {
            float4 a4 = *(const float4*)&As[kk][ty * 4];
            float4 b4 = *(const float4*)&Bs[kk][tx * 4];
            float ar[4] = {a4.x, a4.y, a4.z, a4.w};
            float br[4] = {b4.x, b4.y, b4.z, b4.w};
            #pragma unroll
            for (int r = 0; r < 4; r++)
                #pragma unroll
                for (int c = 0; c < 4; c++)
                    acc[r][c] = fmaf(ar[r], br[c], acc[r][c]);
        }
        __syncthreads();
    }
    #pragma unroll
    for (int r = 0; r < 4; r++) {
        int i = ib + ty * 4 + r;
        if (i >= NPIX) continue;
        #pragma unroll
        for (int c = 0; c < 4; c++) {
            int j = jb + tx * 4 + c;
            if (j < NPIX) d_P[i * NPIX + j] = acc[r][c];
        }
    }
}

// ---------------- phase GEMM: dot = src @ P  (64x64, 4x4) ----------------
__global__ void k_gemmP(const float* __restrict__ src, float* __restrict__ dst,
                        const float* __restrict__ alphas, int phase, int mode) {
    __shared__ float As[16][68];
    __shared__ float Bs[16][68];
    int bb = blockIdx.y * 64, jb = blockIdx.x * 64;
    int tx = threadIdx.x, ty = threadIdx.y;
    int t = ty * 16 + tx;
    float acc[4][4];
    #pragma unroll
    for (int r = 0; r < 4; r++)
        #pragma unroll
        for (int c = 0; c < 4; c++) acc[r][c] = 0.f;

    for (int k0 = 0; k0 < NPIX; k0 += 16) {
        #pragma unroll
        for (int q = t; q < 1024; q += 256) {
            int r = q / 16, kk = q % 16;
            As[kk][r] = (k0 + kk < NPIX) ? src[(bb + r) * NPIX + k0 + kk] : 0.f;
        }
        #pragma unroll
        for (int q = t; q < 1024; q += 256) {
            int kk = q / 64, c = q % 64;
            Bs[kk][c] = (k0 + kk < NPIX && jb + c < NPIX) ? d_P[(k0 + kk) * NPIX + jb + c] : 0.f;
        }
        __syncthreads();
        #pragma unroll
        for (int kk = 0; kk < 16; kk++) {
            float4 a4 = *(const float4*)&As[kk][ty * 4];
            float4 b4 = *(const float4*)&Bs[kk][tx * 4];
            float ar[4] = {a4.x, a4.y, a4.z, a4.w};
            float br[4] = {b4.x, b4.y, b4.z, b4.w};
            #pragma unroll
            for (int r = 0; r < 4; r++)
                #pragma unroll
                for (int c = 0; c < 4; c++)
                    acc[r][c] = fmaf(ar[r], br[c], acc[r][c]);
        }
        __syncthreads();
    }
    float alpha = fabsf(alphas[phase]);
    #pragma unroll
    for (int r = 0; r < 4; r++) {
        int b = bb + ty * 4 + r;
        #pragma unroll
        for (int c = 0; c < 4; c++) {
            int j = jb + tx * 4 + c;
            if (j < NPIX) {
                float dot = acc[r][c];
                float ptb = d_PhiTb[b * NPIX + j];
                if (mode == 0)
                    dst[b * NPIX + j] = src[b * NPIX + j] + alpha * (ptb - dot);
                else
                    dst[b * NPIX + j] = dot - ptb;
            }
        }
    }
}

// ---------------- z step: z = x - |alpha|*dotm ----------------
__global__ void k_zstep(const float* __restrict__ x, float* __restrict__ z,
                        const float* __restrict__ alphas, int phase) {
    float alpha = fabsf(alphas[phase]);
    size_t base = (size_t)blockIdx.x * NPIX;
    for (int j = threadIdx.x; j < NPIX; j += blockDim.x)
        z[base + j] = x[base + j] - alpha * d_dotm[base + j];
}

// ---------------- fused setup GEMMs (blockIdx.z: 0 = PhiTb, 1 = x0) ----------------
__global__ void k_setupF(const float* __restrict__ Phix, const float* __restrict__ Phi,
                         const float* __restrict__ Qinit,
                         float* __restrict__ dPhiTb, float* __restrict__ dx) {
    __shared__ float As[32][33];
    __shared__ float Bs[32][33];
    int tmode = blockIdx.z;
    const float* Bsrc = tmode == 0 ? Phi : Qinit;
    float* dst = tmode == 0 ? dPhiTb : dx;
    int bb = blockIdx.y * 32, jb = blockIdx.x * 32;
    int tx = threadIdx.x, ty = threadIdx.y;
    int t = ty * 16 + tx;
    float acc00 = 0.f, acc01 = 0.f, acc10 = 0.f, acc11 = 0.f;
    for (int k0 = 0; k0 < MDIM; k0 += 32) {
        for (int q = t; q < 1024; q += 256) {
            int kk = q % 32, r = q / 32;
            As[kk][r] = (k0 + kk < MDIM) ? Phix[(bb + r) * MDIM + k0 + kk] : 0.f;
        }
        if (tmode == 0) {
            for (int q = t; q < 1024; q += 256) {
                int kk = q / 32, j = q % 32;
                Bs[kk][j] = (k0 + kk < MDIM && jb + j < NPIX) ? Bsrc[(k0 + kk) * NPIX + jb + j] : 0.f;
            }
        } else {
            for (int q = t; q < 1024; q += 256) {
                int kk = q % 32, j = q / 32;
                Bs[kk][j] = (k0 + kk < MDIM && jb + j < NPIX) ? Bsrc[(jb + j) * MDIM + k0 + kk] : 0.f;
            }
        }
        __syncthreads();
        #pragma unroll
        for (int kk = 0; kk < 32; kk++) {
            float a0 = As[kk][ty*2], a1 = As[kk][ty*2+1];
            float b0 = Bs[kk][tx*2], b1 = Bs[kk][tx*2+1];
            acc00 = fmaf(a0, b0, acc00); acc01 = fmaf(a0, b1, acc01);
            acc10 = fmaf(a1, b0, acc10); acc11 = fmaf(a1, b1, acc11);
        }
        __syncthreads();
    }
    int b0 = bb + ty*2, j0 = jb + tx*2;
    if (j0     < NPIX) dst[(b0  ) * NPIX + j0  ] = acc00;
    if (j0 + 1 < NPIX) dst[(b0  ) * NPIX + j0+1] = acc01;
    if (j0     < NPIX) dst[(b0+1) * NPIX + j0  ] = acc10;
    if (j0 + 1 < NPIX) dst[(b0+1) * NPIX + j0+1] = acc11;
}

// ---------------- heavy conv core: 4 pixels x 8 output channels per thread ----------
// Each weight LDS.128 feeds 8 FFMA2 (4 px x 2 co-pairs): FMA-pipe-bound.
__device__ __forceinline__ void conv_core4(const float* s_in, const float* s_w,
                                           float* __restrict__ outb,
                                           const float* __restrict__ preb,
                                           bool actder, int tid) {
    for (int it = tid; it < NITEM; it += CONV_THREADS) {
        int g = it & 3;          // channel group (8 co)
        int q = it >> 2;         // pixel quad
        int p0 = q * 4;
        int nval = NPIX - p0; if (nval > 4) nval = 4;

        int off[4];
        #pragma unroll
        for (int i = 0; i < 4; i++) {
            int p = p0 + i; if (p > NPIX - 1) p = NPIX - 1;
            int y = p / 33, x = p - y * 33;
            off[i] = y * PADS + x;
        }

        u64 acc[4][4];
        #pragma unroll
        for (int i = 0; i < 4; i++)
            #pragma unroll
            for (int j = 0; j < 4; j++) acc[i][j] = 0ull;

        for (int ci = 0; ci < CC; ci++) {
            const float* sp = s_in + ci * CH_STRIDE;
            float rr[4][9];
            #pragma unroll
            for (int i = 0; i < 4; i++) {
                const float* b = sp + off[i];
                rr[i][0] = b[0];          rr[i][1] = b[1];          rr[i][2] = b[2];
                rr[i][3] = b[PADS];       rr[i][4] = b[PADS+1];     rr[i][5] = b[PADS+2];
                rr[i][6] = b[2*PADS];     rr[i][7] = b[2*PADS+1];   rr[i][8] = b[2*PADS+2];
            }
            const u64* wb = (const u64*)(s_w + ci * 9 * CC) + g * 4;
            #pragma unroll
            for (int k = 0; k < 9; k++) {
                const ulonglong2* w2 = (const ulonglong2*)(wb + k * 16);
                ulonglong2 wA = w2[0];     // co pair 0,1 of group (LDS.128)
                ulonglong2 wB = w2[1];     // co pair 2,3 of group (LDS.128)
                #pragma unroll
                for (int i = 0; i < 4; i++) {
                    u64 vp = pk2(rr[i][k], rr[i][k]);
                    fma2(acc[i][0], vp, wA.x);
                    fma2(acc[i][1], vp, wA.y);
                    fma2(acc[i][2], vp, wB.x);
                    fma2(acc[i][3], vp, wB.y);
                }
            }
        }

        int cobase = g * 8;
        for (int i = 0; i < nval; i++) {
            int p = p0 + i;
            #pragma unroll
            for (int j = 0; j < 4; j++) {
                float2 a = upk2(acc[i][j]);
                int co0 = cobase + 2 * j;
                if (actder) {
                    a.x *= actdf(preb[co0 * NPIX + p]);
                    a.y *= actdf(preb[(co0 + 1) * NPIX + p]);
                }
                outb[co0 * NPIX + p]       = a.x;
                outb[(co0 + 1) * NPIX + p] = a.y;
            }
        }
    }
}

// stage weights into s_w with layout [ci][k][co] (optionally flipped/transposed)
__device__ __forceinline__ void stage_w(const float* __restrict__ w, float* s_w,
                                        bool flip, int tid) {
    for (int idx = tid; idx < CC * CC * 9; idx += CONV_THREADS) {
        int kx = idx % 3, ky = (idx / 3) % 3;
        int i = (idx / 9) % CC, o = idx / (9 * CC);
        float v = w[idx];
        int eci, eco, ek;
        if (flip) { eci = o; eco = i; ek = (2 - ky) * 3 + (2 - kx); }
        else      { eci = i; eco = o; ek = ky * 3 + kx; }
        s_w[(eci * 9 + ek) * CC + eco] = v;
    }
}

// ---------------- heavy 32->32 3x3 conv (fwd or transposed) ----------------
__global__ __launch_bounds__(CONV_THREADS, 1) void k_conv(
        const float* __restrict__ in, const float* __restrict__ w,
        float* __restrict__ out, const float* __restrict__ pre,
        const float* __restrict__ soft, int flags) {
    extern __shared__ float smem[];
    float* s_in = smem;                    // CC * CH_STRIDE
    float* s_w  = smem + CC * CH_STRIDE;   // [ci][k][co]
    int n = blockIdx.x, tid = threadIdx.x;

    for (int i = tid; i < CC * CH_STRIDE; i += CONV_THREADS) s_in[i] = 0.f;
    stage_w(w, s_w, (flags & FLAG_FLIP) != 0, tid);
    __syncthreads();

    const float* inb = in + (size_t)n * CC * NPIX;
    bool act_in = (flags & FLAG_ACT_IN) != 0;
    for (int idx = tid; idx < CC * NPIX; idx += CONV_THREADS) {
        int ci = idx / NPIX, p = idx - ci * NPIX;
        int y = p / 33, x = p - y * 33;
        float v = inb[idx];
        if (act_in) v = actf(v);
        s_in[ci * CH_STRIDE + (y + 1) * PADS + (x + 1)] = v;
    }
    __syncthreads();

    if (flags & FLAG_GNORM) {
        float thr = soft[0] * d_gamma;
        float inv_thr = 1.0f / thr;
        for (int p = tid; p < NPIX; p += CONV_THREADS) {
            int y = p / 33, x = p - y * 33;
            int off = (y + 1) * PADS + (x + 1);
            float v[CC];
            float s = 0.f;
            #pragma unroll
            for (int c = 0; c < CC; c++) {
                v[c] = s_in[c * CH_STRIDE + off];
                s = fmaf(v[c], v[c], s);
            }
            float nrm = sqrtf(s);
            float f = (nrm > thr) ? (1.0f / fmaxf(nrm, 1e-12f)) : inv_thr;
            #pragma unroll
            for (int c = 0; c < CC; c++) s_in[c * CH_STRIDE + off] = v[c] * f;
        }
        __syncthreads();
    }

    conv_core4(s_in, s_w,
               out + (size_t)n * CC * NPIX,
               pre + (size_t)n * CC * NPIX,
               (flags & FLAG_ACTDER) != 0, tid);
}

// ---------------- fused conv1 + conv2: z -> x1 (gmem) -> act -> conv2 -> x2 ----------
__global__ __launch_bounds__(CONV_THREADS, 1) void k_conv12(
        const float* __restrict__ z, const float* __restrict__ w1,
        const float* __restrict__ w2,
        float* __restrict__ x1out, float* __restrict__ x2out) {
    extern __shared__ float smem[];
    float* s_in = smem;                           // CC * CH_STRIDE (act(x1), padded)
    float* s_w  = s_in + CC * CH_STRIDE;          // CC*CC*9 (c2 weights)
    float* s_z  = s_w + CC * CC * 9;              // CH_STRIDE (padded z)
    float* s_w1 = s_z + CH_STRIDE;                // 9*CC  [k][co]
    int n = blockIdx.x, tid = threadIdx.x;

    for (int i = tid; i < CC * CH_STRIDE; i += CONV_THREADS) s_in[i] = 0.f;
    for (int i = tid; i < CH_STRIDE; i += CONV_THREADS) s_z[i] = 0.f;
    stage_w(w2, s_w, false, tid);
    for (int idx = tid; idx < CC * 9; idx += CONV_THREADS) {
        int o = idx / 9, k = idx % 9;
        s_w1[k * CC + o] = w1[idx];
    }
    __syncthreads();

    const float* zb = z + (size_t)n * NPIX;
    for (int p = tid; p < NPIX; p += CONV_THREADS) {
        int y = p / 33, x = p - y * 33;
        s_z[(y + 1) * PADS + (x + 1)] = zb[p];
    }
    __syncthreads();

    // conv1: thread per pixel, all 32 output channels
    float* x1b = x1out + (size_t)n * CC * NPIX;
    for (int p = tid; p < NPIX; p += CONV_THREADS) {
        int y = p / 33, x = p - y * 33;
        const float* sp = s_z + y * PADS + x;
        float zv[9];
        zv[0]=sp[0]; zv[1]=sp[1]; zv[2]=sp[2];
        zv[3]=sp[PADS]; zv[4]=sp[PADS+1]; zv[5]=sp[PADS+2];
        zv[6]=sp[2*PADS]; zv[7]=sp[2*PADS+1]; zv[8]=sp[2*PADS+2];
        float acc[CC];
        #pragma unroll
        for (int co = 0; co < CC; co++) acc[co] = 0.f;
        #pragma unroll
        for (int k = 0; k < 9; k++) {
            #pragma unroll
            for (int c4 = 0; c4 < 8; c4++) {
                float4 wv = *(const float4*)(s_w1 + k * CC + c4 * 4);
                acc[c4*4+0] = fmaf(zv[k], wv.x, acc[c4*4+0]);
                acc[c4*4+1] = fmaf(zv[k], wv.y, acc[c4*4+1]);
                acc[c4*4+2] = fmaf(zv[k], wv.z, acc[c4*4+2]);
                acc[c4*4+3] = fmaf(zv[k], wv.w, acc[c4*4+3]);
            }
        }
        int off = (y + 1) * PADS + (x + 1);
        #pragma unroll
        for (int co = 0; co < CC; co++) {
            x1b[co * NPIX + p] = acc[co];
            s_in[co * CH_STRIDE + off] = actf(acc[co]);
        }
    }
    __syncthreads();

    conv_core4(s_in, s_w, x2out + (size_t)n * CC * NPIX,
               x1out, false, tid);
}

// ---------------- convT1 (32 -> 1), fused with x/gphi update ----------------
__global__ __launch_bounds__(CONV_THREADS, 1) void k_convT1(
        const float* __restrict__ in, const float* __restrict__ w1,
        const float* __restrict__ z, float* __restrict__ x,
        const float* __restrict__ dotm, float* __restrict__ gphi,
        const float* __restrict__ alphas, const float* __restrict__ betas,
        int phase, int mode, float* __restrict__ out_extra) {
    extern __shared__ float smem[];
    float* s_in = smem;                 // CC * CH_STRIDE
    __shared__ float s_w[CC * 9];       // flipped [o][k]
    int n = blockIdx.x, tid = threadIdx.x;
    for (int i = tid; i < CC * CH_STRIDE; i += CONV_THREADS) s_in[i] = 0.f;
    for (int idx = tid; idx < CC * 9; idx += CONV_THREADS) {
        int o = idx / 9, k = idx % 9;
        int ky = k / 3, kx = k % 3;
        s_w[o * 9 + (2 - ky) * 3 + (2 - kx)] = w1[idx];
    }
    __syncthreads();
    const float* inb = in + (size_t)n * CC * NPIX;
    for (int idx = tid; idx < CC * NPIX; idx += CONV_THREADS) {
        int ci = idx / NPIX, p = idx - ci * NPIX;
        int y = p / 33, x2 = p - y * 33;
        s_in[ci * CH_STRIDE + (y + 1) * PADS + (x2 + 1)] = inb[idx];
    }
    __syncthreads();

    float a = fabsf(alphas[phase]), b = fabsf(betas[phase]);
    float tau = a * b / (a + b);

    for (int p = tid; p < NPIX; p += CONV_THREADS) {
        int y = p / 33, xx = p - y * 33;
        float acc = 0.f;
        const float* sbase = s_in + y * PADS + xx;
        for (int o = 0; o < CC; o++) {
            const float* sp = sbase + o * CH_STRIDE;
            const float* wp = s_w + o * 9;
            #pragma unroll
            for (int k = 0; k < 9; k++)
                acc = fmaf(sp[(k / 3) * PADS + (k % 3)], wp[k], acc);
        }
        size_t off = (size_t)n * NPIX + p;
        if (mode == 0) {
            float nx = z[off] - tau * acc;
            x[off] = nx;
            if (out_extra) out_extra[off] = nx;
        } else {
            gphi[off] = dotm[off] + acc;
        }
    }
}

// ---------------- row norms + gamma update ----------------
__global__ void k_rownorm(const float* __restrict__ gphi) {
    __shared__ float red[256];
    int bidx = blockIdx.x;
    float s = 0.f;
    for (int j = threadIdx.x; j < NPIX; j += 256) {
        float v = gphi[(size_t)bidx * NPIX + j];
        s = fmaf(v, v, s);
    }
    red[threadIdx.x] = s;
    __syncthreads();
    for (int off = 128; off > 0; off >>= 1) {
        if (threadIdx.x < off) red[threadIdx.x] += red[threadIdx.x + off];
        __syncthreads();
    }
    if (threadIdx.x == 0) d_ngrad[bidx] = sqrtf(red[0]);
}

__global__ void k_gamma(const float* __restrict__ soft_thr) {
    __shared__ float red[256];
    red[threadIdx.x] = d_ngrad[threadIdx.x];
    __syncthreads();
    for (int off = 128; off > 0; off >>= 1) {
        if (threadIdx.x < off) red[threadIdx.x] += red[threadIdx.x + off];
        __syncthreads();
    }
    if (threadIdx.x == 0) {
        float mean = red[0] / (float)BB;
        float g = d_gamma;
        if (mean < 15000.0f * g * soft_thr[0]) g *= 0.9f;
        d_gamma = g;
    }
}

// ---------------- host orchestration ----------------
#define SMEM_CONV ((CC * CH_STRIDE + CC * CC * 9) * (int)sizeof(float))              /* 198144 */
#define SMEM_C12  ((CC * CH_STRIDE + CC * CC * 9 + CH_STRIDE + 9 * CC) * (int)sizeof(float)) /* 204336 */
#define SMEM_T1   ((CC * CH_STRIDE) * (int)sizeof(float))                            /* 161280 */

static void grad_r_chain(const float* src, const float* c1, const float* c2,
                         const float* c3, const float* c4, const float* soft,
                         float* px1, float* px2, float* px3, float* pg, float* pbA,
                         const float* pz, float* px, const float* pdotm, float* pgphi,
                         const float* alphas, const float* betas,
                         int phase, int mode, float* out_extra) {
    k_conv12<<<BB, CONV_THREADS, SMEM_C12>>>(src, c1, c2, px1, px2);
    k_conv<<<BB, CONV_THREADS, SMEM_CONV>>>(px2, c3, px3, px1, soft, FLAG_ACT_IN);
    k_conv<<<BB, CONV_THREADS, SMEM_CONV>>>(px3, c4, pg,  px1, soft, FLAG_ACT_IN);
    k_conv<<<BB, CONV_THREADS, SMEM_CONV>>>(pg,  c4, pbA, px3, soft, FLAG_FLIP | FLAG_ACTDER | FLAG_GNORM);
    k_conv<<<BB, CONV_THREADS, SMEM_CONV>>>(pbA, c3, pg,  px2, soft, FLAG_FLIP | FLAG_ACTDER);
    k_conv<<<BB, CONV_THREADS, SMEM_CONV>>>(pg,  c2, pbA, px1, soft, FLAG_FLIP | FLAG_ACTDER);
    k_convT1<<<BB, CONV_THREADS, SMEM_T1>>>(pbA, c1, pz, px, pdotm, pgphi,
                                            alphas, betas, phase, mode, out_extra);
}

extern "C" void kernel_launch(void* const* d_in, const int* in_sizes, int n_in,
                              void* d_out, int out_size) {
    (void)in_sizes; (void)n_in; (void)out_size;
    const float* Phix   = (const float*)d_in[0];
    const float* Phi    = (const float*)d_in[1];
    const float* Qinit  = (const float*)d_in[2];
    const float* soft   = (const float*)d_in[3];
    const float* alphas = (const float*)d_in[4];
    const float* betas  = (const float*)d_in[5];
    const float* c1     = (const float*)d_in[6];
    const float* c2     = (const float*)d_in[7];
    const float* c3     = (const float*)d_in[8];
    const float* c4     = (const float*)d_in[9];
    float* out = (float*)d_out;

    cudaFuncSetAttribute(k_conv,   cudaFuncAttributeMaxDynamicSharedMemorySize, SMEM_CONV);
    cudaFuncSetAttribute(k_conv12, cudaFuncAttributeMaxDynamicSharedMemorySize, SMEM_C12);
    cudaFuncSetAttribute(k_convT1, cudaFuncAttributeMaxDynamicSharedMemorySize, SMEM_T1);

    float *px, *pz, *pgphi, *pdotm, *px1, *px2, *px3, *pg, *pbA, *pPhiTb;
    cudaGetSymbolAddress((void**)&px,     d_x);
    cudaGetSymbolAddress((void**)&pz,     d_z);
    cudaGetSymbolAddress((void**)&pgphi,  d_gphi);
    cudaGetSymbolAddress((void**)&pdotm,  d_dotm);
    cudaGetSymbolAddress((void**)&px1,    d_x1);
    cudaGetSymbolAddress((void**)&px2,    d_x2);
    cudaGetSymbolAddress((void**)&px3,    d_x3);
    cudaGetSymbolAddress((void**)&pg,     d_g);
    cudaGetSymbolAddress((void**)&pbA,    d_bA);
    cudaGetSymbolAddress((void**)&pPhiTb, d_PhiTb);

    dim3 tb16(16, 16);
    k_phitphi64<<<dim3(18, 18), tb16>>>(Phi);                       // + gamma init
    k_setupF<<<dim3(35, 8, 2), tb16>>>(Phix, Phi, Qinit, pPhiTb, px);

    for (int p = 0; p < 3; p++) {
        if (p == 0)
            k_gemmP<<<dim3(18, 4), tb16>>>(px, pz, alphas, p, 0);
        else
            k_zstep<<<BB, 256>>>(px, pz, alphas, p);
        grad_r_chain(pz, c1, c2, c3, c4, soft, px1, px2, px3, pg, pbA,
                     pz, px, pdotm, pgphi, alphas, betas, p, 0,
                     (p == 2) ? out : nullptr);
        if (p < 2) {
            k_gemmP<<<dim3(18, 4), tb16>>>(px, pdotm, alphas, p, 1);
            grad_r_chain(px, c1, c2, c3, c4, soft, px1, px2, px3, pg, pbA,
                         pz, px, pdotm, pgphi, alphas, betas, p, 1, nullptr);
            k_rownorm<<<BB, 256>>>(pgphi);
            k_gamma<<<1, 256>>>(soft);
        }
    }
}

// round 5
// speedup vs baseline: 1.2583x; 1.0857x over previous
#include <cuda_runtime.h>
#include <math.h>

#define BB   256
#define NPIX 1089
#define MDIM 272
#define CC   32
#define PADS 36
#define CH_STRIDE (35*PADS)   /* 1260 floats per padded channel */
#define CONV_THREADS 384
#define NITEM 792             /* 6 y-strips * 33 x * 4 channel-groups */

#define FLAG_ACT_IN 1
#define FLAG_FLIP   2
#define FLAG_ACTDER 4
#define FLAG_GNORM  8

typedef unsigned long long u64;

// ---------------- device state (static, no allocation) ----------------
__device__ float d_P[NPIX*NPIX];
__device__ float d_PhiTb[BB*NPIX];
__device__ float d_x[BB*NPIX];
__device__ float d_z[BB*NPIX];
__device__ float d_gphi[BB*NPIX];
__device__ float d_dotm[BB*NPIX];
__device__ float d_x1[BB*CC*NPIX];
__device__ float d_x2[BB*CC*NPIX];
__device__ float d_x3[BB*CC*NPIX];
__device__ float d_g [BB*CC*NPIX];
__device__ float d_bA[BB*CC*NPIX];
__device__ float d_ngrad[BB];
__device__ float d_gamma;

// ---------------- packed f32x2 helpers ----------------
__device__ __forceinline__ u64 pk2(float a, float b) {
    u64 r; asm("mov.b64 %0, {%1,%2};" : "=l"(r) : "f"(a), "f"(b)); return r;
}
__device__ __forceinline__ void fma2(u64& d, u64 a, u64 b) {
    asm("fma.rn.f32x2 %0, %1, %2, %3;" : "=l"(d) : "l"(a), "l"(b), "l"(d));
}
__device__ __forceinline__ float2 upk2(u64 v) {
    float2 f; asm("mov.b64 {%0,%1}, %2;" : "=f"(f.x), "=f"(f.y) : "l"(v)); return f;
}

// ---------------- activation (eq. 33), DELTA = 0.01 ----------------
__device__ __forceinline__ float actf(float v) {
    if (fabsf(v) > 0.01f) return fmaxf(v, 0.0f);
    return fmaf(v*v, 25.0f, fmaf(v, 0.5f, 0.0025f));
}
__device__ __forceinline__ float actdf(float v) {
    if (fabsf(v) > 0.01f) return v > 0.0f ? 1.0f : 0.0f;
    return fmaf(v, 50.0f, 0.5f);
}

// ---------------- GEMM: P = Phi^T Phi (64x64 tiles, 4x4 per thread) ----------------
__global__ void k_phitphi64(const float* __restrict__ Phi) {
    if (blockIdx.x == 0 && blockIdx.y == 0 && threadIdx.x == 0 && threadIdx.y == 0)
        d_gamma = 1.0f;
    __shared__ float As[16][68];
    __shared__ float Bs[16][68];
    int ib = blockIdx.y * 64, jb = blockIdx.x * 64;
    int tx = threadIdx.x, ty = threadIdx.y;
    int t = ty * 16 + tx;
    float acc[4][4];
    #pragma unroll
    for (int r = 0; r < 4; r++)
        #pragma unroll
        for (int c = 0; c < 4; c++) acc[r][c] = 0.f;

    for (int k0 = 0; k0 < MDIM; k0 += 16) {
        #pragma unroll
        for (int q = t; q < 1024; q += 256) {
            int kk = q / 64, r = q % 64;
            As[kk][r] = (ib + r < NPIX) ? Phi[(k0 + kk) * NPIX + ib + r] : 0.f;
            Bs[kk][r] = (jb + r < NPIX) ? Phi[(k0 + kk) * NPIX + jb + r] : 0.f;
        }
        __syncthreads();
        #pragma unroll
        for (int kk = 0; kk < 16; kk++) {
            float4 a4 = *(const float4*)&As[kk][ty * 4];
            float4 b4 = *(const float4*)&Bs[kk][tx * 4];
            float ar[4] = {a4.x, a4.y, a4.z, a4.w};
            float br[4] = {b4.x, b4.y, b4.z, b4.w};
            #pragma unroll
            for (int r = 0; r < 4; r++)
                #pragma unroll
                for (int c = 0; c < 4; c++)
                    acc[r][c] = fmaf(ar[r], br[c], acc[r][c]);
        }
        __syncthreads();
    }
    #pragma unroll
    for (int r = 0; r < 4; r++) {
        int i = ib + ty * 4 + r;
        if (i >= NPIX) continue;
        #pragma unroll
        for (int c = 0; c < 4; c++) {
            int j = jb + tx * 4 + c;
            if (j < NPIX) d_P[i * NPIX + j] = acc[r][c];
        }
    }
}

// ---------------- phase GEMM: dot = src @ P  (64x64, 4x4) ----------------
__global__ void k_gemmP(const float* __restrict__ src, float* __restrict__ dst,
                        const float* __restrict__ alphas, int phase, int mode) {
    __shared__ float As[16][68];
    __shared__ float Bs[16][68];
    int bb = blockIdx.y * 64, jb = blockIdx.x * 64;
    int tx = threadIdx.x, ty = threadIdx.y;
    int t = ty * 16 + tx;
    float acc[4][4];
    #pragma unroll
    for (int r = 0; r < 4; r++)
        #pragma unroll
        for (int c = 0; c < 4; c++) acc[r][c] = 0.f;

    for (int k0 = 0; k0 < NPIX; k0 += 16) {
        #pragma unroll
        for (int q = t; q < 1024; q += 256) {
            int r = q / 16, kk = q % 16;
            As[kk][r] = (k0 + kk < NPIX) ? src[(bb + r) * NPIX + k0 + kk] : 0.f;
        }
        #pragma unroll
        for (int q = t; q < 1024; q += 256) {
            int kk = q / 64, c = q % 64;
            Bs[kk][c] = (k0 + kk < NPIX && jb + c < NPIX) ? d_P[(k0 + kk) * NPIX + jb + c] : 0.f;
        }
        __syncthreads();
        #pragma unroll
        for (int kk = 0; kk < 16; kk++) {
            float4 a4 = *(const float4*)&As[kk][ty * 4];
            float4 b4 = *(const float4*)&Bs[kk][tx * 4];
            float ar[4] = {a4.x, a4.y, a4.z, a4.w};
            float br[4] = {b4.x, b4.y, b4.z, b4.w};
            #pragma unroll
            for (int r = 0; r < 4; r++)
                #pragma unroll
                for (int c = 0; c < 4; c++)
                    acc[r][c] = fmaf(ar[r], br[c], acc[r][c]);
        }
        __syncthreads();
    }
    float alpha = fabsf(alphas[phase]);
    #pragma unroll
    for (int r = 0; r < 4; r++) {
        int b = bb + ty * 4 + r;
        #pragma unroll
        for (int c = 0; c < 4; c++) {
            int j = jb + tx * 4 + c;
            if (j < NPIX) {
                float dot = acc[r][c];
                float ptb = d_PhiTb[b * NPIX + j];
                if (mode == 0)
                    dst[b * NPIX + j] = src[b * NPIX + j] + alpha * (ptb - dot);
                else
                    dst[b * NPIX + j] = dot - ptb;
            }
        }
    }
}

// ---------------- z step: z = x - |alpha|*dotm ----------------
__global__ void k_zstep(const float* __restrict__ x, float* __restrict__ z,
                        const float* __restrict__ alphas, int phase) {
    float alpha = fabsf(alphas[phase]);
    size_t base = (size_t)blockIdx.x * NPIX;
    for (int j = threadIdx.x; j < NPIX; j += blockDim.x)
        z[base + j] = x[base + j] - alpha * d_dotm[base + j];
}

// ---------------- fused setup GEMMs (blockIdx.z: 0 = PhiTb, 1 = x0) ----------------
__global__ void k_setupF(const float* __restrict__ Phix, const float* __restrict__ Phi,
                         const float* __restrict__ Qinit,
                         float* __restrict__ dPhiTb, float* __restrict__ dx) {
    __shared__ float As[32][33];
    __shared__ float Bs[32][33];
    int tmode = blockIdx.z;
    const float* Bsrc = tmode == 0 ? Phi : Qinit;
    float* dst = tmode == 0 ? dPhiTb : dx;
    int bb = blockIdx.y * 32, jb = blockIdx.x * 32;
    int tx = threadIdx.x, ty = threadIdx.y;
    int t = ty * 16 + tx;
    float acc00 = 0.f, acc01 = 0.f, acc10 = 0.f, acc11 = 0.f;
    for (int k0 = 0; k0 < MDIM; k0 += 32) {
        for (int q = t; q < 1024; q += 256) {
            int kk = q % 32, r = q / 32;
            As[kk][r] = (k0 + kk < MDIM) ? Phix[(bb + r) * MDIM + k0 + kk] : 0.f;
        }
        if (tmode == 0) {
            for (int q = t; q < 1024; q += 256) {
                int kk = q / 32, j = q % 32;
                Bs[kk][j] = (k0 + kk < MDIM && jb + j < NPIX) ? Bsrc[(k0 + kk) * NPIX + jb + j] : 0.f;
            }
        } else {
            for (int q = t; q < 1024; q += 256) {
                int kk = q % 32, j = q / 32;
                Bs[kk][j] = (k0 + kk < MDIM && jb + j < NPIX) ? Bsrc[(jb + j) * MDIM + k0 + kk] : 0.f;
            }
        }
        __syncthreads();
        #pragma unroll
        for (int kk = 0; kk < 32; kk++) {
            float a0 = As[kk][ty*2], a1 = As[kk][ty*2+1];
            float b0 = Bs[kk][tx*2], b1 = Bs[kk][tx*2+1];
            acc00 = fmaf(a0, b0, acc00); acc01 = fmaf(a0, b1, acc01);
            acc10 = fmaf(a1, b0, acc10); acc11 = fmaf(a1, b1, acc11);
        }
        __syncthreads();
    }
    int b0 = bb + ty*2, j0 = jb + tx*2;
    if (j0     < NPIX) dst[(b0  ) * NPIX + j0  ] = acc00;
    if (j0 + 1 < NPIX) dst[(b0  ) * NPIX + j0+1] = acc01;
    if (j0     < NPIX) dst[(b0+1) * NPIX + j0  ] = acc10;
    if (j0 + 1 < NPIX) dst[(b0+1) * NPIX + j0+1] = acc11;
}

// ---------------- heavy conv core: vertical 6-pixel strip x 8 output channels ----------
// Patch reuse: 6 pixels (same x, y0..y0+5) share an 8-row x 3-col input patch
// => 24 input LDS per ci for 216 FFMA2 (432 MAC). FMA-pipe-bound.
__device__ __forceinline__ void conv_core6(const float* s_in, const float* s_w,
                                           float* __restrict__ outb,
                                           const float* __restrict__ preb,
                                           bool actder, int tid) {
    for (int it = tid; it < NITEM; it += CONV_THREADS) {
        int g  = it & 3;          // channel group (8 co)
        int q  = it >> 2;         // strip index
        int yq = q / 33;
        int x  = q - yq * 33;
        int y0 = yq * 6;
        int nval = 33 - y0; if (nval > 6) nval = 6;

        // acc[i][j]: pixel i (y0+i), co-pair j of group g
        u64 acc[6][4];
        #pragma unroll
        for (int i = 0; i < 6; i++)
            #pragma unroll
            for (int j = 0; j < 4; j++) acc[i][j] = 0ull;

        for (int ci = 0; ci < CC; ci++) {
            const float* sp = s_in + ci * CH_STRIDE;
            // patch rows: pixel-space y0-1 .. y0+6 => stored rows y0 .. y0+7 (clamp to 34)
            float patch[8][3];
            #pragma unroll
            for (int r = 0; r < 8; r++) {
                int sr = y0 + r; if (sr > 34) sr = 34;
                const float* rp = sp + sr * PADS + x;   // stored col for pixel-space x-1 is x
                patch[r][0] = rp[0];
                patch[r][1] = rp[1];
                patch[r][2] = rp[2];
            }
            const u64* wb = (const u64*)(s_w + ci * 9 * CC) + g * 4;
            #pragma unroll
            for (int ky = 0; ky < 3; ky++) {
                #pragma unroll
                for (int kx = 0; kx < 3; kx++) {
                    int k = ky * 3 + kx;
                    const ulonglong2* w2 = (const ulonglong2*)(wb + k * 16);
                    ulonglong2 wA = w2[0];   // co pair 0,1 of group (LDS.128)
                    ulonglong2 wB = w2[1];   // co pair 2,3 of group (LDS.128)
                    #pragma unroll
                    for (int i = 0; i < 6; i++) {
                        float v = patch[i + ky][kx];
                        u64 vp = pk2(v, v);
                        fma2(acc[i][0], vp, wA.x);
                        fma2(acc[i][1], vp, wA.y);
                        fma2(acc[i][2], vp, wB.x);
                        fma2(acc[i][3], vp, wB.y);
                    }
                }
            }
        }

        int cobase = g * 8;
        for (int i = 0; i < nval; i++) {
            int p = (y0 + i) * 33 + x;
            #pragma unroll
            for (int j = 0; j < 4; j++) {
                float2 a = upk2(acc[i][j]);
                int co0 = cobase + 2 * j;
                if (actder) {
                    a.x *= actdf(preb[co0 * NPIX + p]);
                    a.y *= actdf(preb[(co0 + 1) * NPIX + p]);
                }
                outb[co0 * NPIX + p]       = a.x;
                outb[(co0 + 1) * NPIX + p] = a.y;
            }
        }
    }
}

// stage weights into s_w with layout [ci][k][co] (optionally flipped/transposed)
__device__ __forceinline__ void stage_w(const float* __restrict__ w, float* s_w,
                                        bool flip, int tid) {
    for (int idx = tid; idx < CC * CC * 9; idx += CONV_THREADS) {
        int kx = idx % 3, ky = (idx / 3) % 3;
        int i = (idx / 9) % CC, o = idx / (9 * CC);
        float v = w[idx];
        int eci, eco, ek;
        if (flip) { eci = o; eco = i; ek = (2 - ky) * 3 + (2 - kx); }
        else      { eci = i; eco = o; ek = ky * 3 + kx; }
        s_w[(eci * 9 + ek) * CC + eco] = v;
    }
}

// ---------------- heavy 32->32 3x3 conv (fwd or transposed) ----------------
__global__ __launch_bounds__(CONV_THREADS, 1) void k_conv(
        const float* __restrict__ in, const float* __restrict__ w,
        float* __restrict__ out, const float* __restrict__ pre,
        const float* __restrict__ soft, int flags) {
    extern __shared__ float smem[];
    float* s_in = smem;                    // CC * CH_STRIDE
    float* s_w  = smem + CC * CH_STRIDE;   // [ci][k][co]
    int n = blockIdx.x, tid = threadIdx.x;

    for (int i = tid; i < CC * CH_STRIDE; i += CONV_THREADS) s_in[i] = 0.f;
    stage_w(w, s_w, (flags & FLAG_FLIP) != 0, tid);
    __syncthreads();

    const float* inb = in + (size_t)n * CC * NPIX;
    bool act_in = (flags & FLAG_ACT_IN) != 0;
    for (int idx = tid; idx < CC * NPIX; idx += CONV_THREADS) {
        int ci = idx / NPIX, p = idx - ci * NPIX;
        int y = p / 33, x = p - y * 33;
        float v = inb[idx];
        if (act_in) v = actf(v);
        s_in[ci * CH_STRIDE + (y + 1) * PADS + (x + 1)] = v;
    }
    __syncthreads();

    if (flags & FLAG_GNORM) {
        float thr = soft[0] * d_gamma;
        float inv_thr = 1.0f / thr;
        for (int p = tid; p < NPIX; p += CONV_THREADS) {
            int y = p / 33, x = p - y * 33;
            int off = (y + 1) * PADS + (x + 1);
            float v[CC];
            float s = 0.f;
            #pragma unroll
            for (int c = 0; c < CC; c++) {
                v[c] = s_in[c * CH_STRIDE + off];
                s = fmaf(v[c], v[c], s);
            }
            float nrm = sqrtf(s);
            float f = (nrm > thr) ? (1.0f / fmaxf(nrm, 1e-12f)) : inv_thr;
            #pragma unroll
            for (int c = 0; c < CC; c++) s_in[c * CH_STRIDE + off] = v[c] * f;
        }
        __syncthreads();
    }

    conv_core6(s_in, s_w,
               out + (size_t)n * CC * NPIX,
               pre + (size_t)n * CC * NPIX,
               (flags & FLAG_ACTDER) != 0, tid);
}

// ---------------- fused conv1 + conv2: z -> x1 (gmem) -> act -> conv2 -> x2 ----------
__global__ __launch_bounds__(CONV_THREADS, 1) void k_conv12(
        const float* __restrict__ z, const float* __restrict__ w1,
        const float* __restrict__ w2,
        float* __restrict__ x1out, float* __restrict__ x2out) {
    extern __shared__ float smem[];
    float* s_in = smem;                           // CC * CH_STRIDE (act(x1), padded)
    float* s_w  = s_in + CC * CH_STRIDE;          // CC*CC*9 (c2 weights)
    float* s_z  = s_w + CC * CC * 9;              // CH_STRIDE (padded z)
    float* s_w1 = s_z + CH_STRIDE;                // 9*CC  [k][co]
    int n = blockIdx.x, tid = threadIdx.x;

    for (int i = tid; i < CC * CH_STRIDE; i += CONV_THREADS) s_in[i] = 0.f;
    for (int i = tid; i < CH_STRIDE; i += CONV_THREADS) s_z[i] = 0.f;
    stage_w(w2, s_w, false, tid);
    for (int idx = tid; idx < CC * 9; idx += CONV_THREADS) {
        int o = idx / 9, k = idx % 9;
        s_w1[k * CC + o] = w1[idx];
    }
    __syncthreads();

    const float* zb = z + (size_t)n * NPIX;
    for (int p = tid; p < NPIX; p += CONV_THREADS) {
        int y = p / 33, x = p - y * 33;
        s_z[(y + 1) * PADS + (x + 1)] = zb[p];
    }
    __syncthreads();

    // conv1: thread per pixel, all 32 output channels
    float* x1b = x1out + (size_t)n * CC * NPIX;
    for (int p = tid; p < NPIX; p += CONV_THREADS) {
        int y = p / 33, x = p - y * 33;
        const float* sp = s_z + y * PADS + x;
        float zv[9];
        zv[0]=sp[0]; zv[1]=sp[1]; zv[2]=sp[2];
        zv[3]=sp[PADS]; zv[4]=sp[PADS+1]; zv[5]=sp[PADS+2];
        zv[6]=sp[2*PADS]; zv[7]=sp[2*PADS+1]; zv[8]=sp[2*PADS+2];
        float acc[CC];
        #pragma unroll
        for (int co = 0; co < CC; co++) acc[co] = 0.f;
        #pragma unroll
        for (int k = 0; k < 9; k++) {
            #pragma unroll
            for (int c4 = 0; c4 < 8; c4++) {
                float4 wv = *(const float4*)(s_w1 + k * CC + c4 * 4);
                acc[c4*4+0] = fmaf(zv[k], wv.x, acc[c4*4+0]);
                acc[c4*4+1] = fmaf(zv[k], wv.y, acc[c4*4+1]);
                acc[c4*4+2] = fmaf(zv[k], wv.z, acc[c4*4+2]);
                acc[c4*4+3] = fmaf(zv[k], wv.w, acc[c4*4+3]);
            }
        }
        int off = (y + 1) * PADS + (x + 1);
        #pragma unroll
        for (int co = 0; co < CC; co++) {
            x1b[co * NPIX + p] = acc[co];
            s_in[co * CH_STRIDE + off] = actf(acc[co]);
        }
    }
    __syncthreads();

    conv_core6(s_in, s_w, x2out + (size_t)n * CC * NPIX,
               x1out, false, tid);
}

// ---------------- convT1 (32 -> 1), fused with x/gphi update ----------------
__global__ __launch_bounds__(CONV_THREADS, 1) void k_convT1(
        const float* __restrict__ in, const float* __restrict__ w1,
        const float* __restrict__ z, float* __restrict__ x,
        const float* __restrict__ dotm, float* __restrict__ gphi,
        const float* __restrict__ alphas, const float* __restrict__ betas,
        int phase, int mode, float* __restrict__ out_extra) {
    extern __shared__ float smem[];
    float* s_in = smem;                 // CC * CH_STRIDE
    __shared__ float s_w[CC * 9];       // flipped [o][k]
    int n = blockIdx.x, tid = threadIdx.x;
    for (int i = tid; i < CC * CH_STRIDE; i += CONV_THREADS) s_in[i] = 0.f;
    for (int idx = tid; idx < CC * 9; idx += CONV_THREADS) {
        int o = idx / 9, k = idx % 9;
        int ky = k / 3, kx = k % 3;
        s_w[o * 9 + (2 - ky) * 3 + (2 - kx)] = w1[idx];
    }
    __syncthreads();
    const float* inb = in + (size_t)n * CC * NPIX;
    for (int idx = tid; idx < CC * NPIX; idx += CONV_THREADS) {
        int ci = idx / NPIX, p = idx - ci * NPIX;
        int y = p / 33, x2 = p - y * 33;
        s_in[ci * CH_STRIDE + (y + 1) * PADS + (x2 + 1)] = inb[idx];
    }
    __syncthreads();

    float a = fabsf(alphas[phase]), b = fabsf(betas[phase]);
    float tau = a * b / (a + b);

    for (int p = tid; p < NPIX; p += CONV_THREADS) {
        int y = p / 33, xx = p - y * 33;
        float acc = 0.f;
        const float* sbase = s_in + y * PADS + xx;
        for (int o = 0; o < CC; o++) {
            const float* sp = sbase + o * CH_STRIDE;
            const float* wp = s_w + o * 9;
            #pragma unroll
            for (int k = 0; k < 9; k++)
                acc = fmaf(sp[(k / 3) * PADS + (k % 3)], wp[k], acc);
        }
        size_t off = (size_t)n * NPIX + p;
        if (mode == 0) {
            float nx = z[off] - tau * acc;
            x[off] = nx;
            if (out_extra) out_extra[off] = nx;
        } else {
            gphi[off] = dotm[off] + acc;
        }
    }
}

// ---------------- row norms + gamma update ----------------
__global__ void k_rownorm(const float* __restrict__ gphi) {
    __shared__ float red[256];
    int bidx = blockIdx.x;
    float s = 0.f;
    for (int j = threadIdx.x; j < NPIX; j += 256) {
        float v = gphi[(size_t)bidx * NPIX + j];
        s = fmaf(v, v, s);
    }
    red[threadIdx.x] = s;
    __syncthreads();
    for (int off = 128; off > 0; off >>= 1) {
        if (threadIdx.x < off) red[threadIdx.x] += red[threadIdx.x + off];
        __syncthreads();
    }
    if (threadIdx.x == 0) d_ngrad[bidx] = sqrtf(red[0]);
}

__global__ void k_gamma(const float* __restrict__ soft_thr) {
    __shared__ float red[256];
    red[threadIdx.x] = d_ngrad[threadIdx.x];
    __syncthreads();
    for (int off = 128; off > 0; off >>= 1) {
        if (threadIdx.x < off) red[threadIdx.x] += red[threadIdx.x + off];
        __syncthreads();
    }
    if (threadIdx.x == 0) {
        float mean = red[0] / (float)BB;
        float g = d_gamma;
        if (mean < 15000.0f * g * soft_thr[0]) g *= 0.9f;
        d_gamma = g;
    }
}

// ---------------- host orchestration ----------------
#define SMEM_CONV ((CC * CH_STRIDE + CC * CC * 9) * (int)sizeof(float))              /* 198144 */
#define SMEM_C12  ((CC * CH_STRIDE + CC * CC * 9 + CH_STRIDE + 9 * CC) * (int)sizeof(float)) /* 204336 */
#define SMEM_T1   ((CC * CH_STRIDE) * (int)sizeof(float))                            /* 161280 */

static void grad_r_chain(const float* src, const float* c1, const float* c2,
                         const float* c3, const float* c4, const float* soft,
                         float* px1, float* px2, float* px3, float* pg, float* pbA,
                         const float* pz, float* px, const float* pdotm, float* pgphi,
                         const float* alphas, const float* betas,
                         int phase, int mode, float* out_extra) {
    k_conv12<<<BB, CONV_THREADS, SMEM_C12>>>(src, c1, c2, px1, px2);
    k_conv<<<BB, CONV_THREADS, SMEM_CONV>>>(px2, c3, px3, px1, soft, FLAG_ACT_IN);
    k_conv<<<BB, CONV_THREADS, SMEM_CONV>>>(px3, c4, pg,  px1, soft, FLAG_ACT_IN);
    k_conv<<<BB, CONV_THREADS, SMEM_CONV>>>(pg,  c4, pbA, px3, soft, FLAG_FLIP | FLAG_ACTDER | FLAG_GNORM);
    k_conv<<<BB, CONV_THREADS, SMEM_CONV>>>(pbA, c3, pg,  px2, soft, FLAG_FLIP | FLAG_ACTDER);
    k_conv<<<BB, CONV_THREADS, SMEM_CONV>>>(pg,  c2, pbA, px1, soft, FLAG_FLIP | FLAG_ACTDER);
    k_convT1<<<BB, CONV_THREADS, SMEM_T1>>>(pbA, c1, pz, px, pdotm, pgphi,
                                            alphas, betas, phase, mode, out_extra);
}

extern "C" void kernel_launch(void* const* d_in, const int* in_sizes, int n_in,
                              void* d_out, int out_size) {
    (void)in_sizes; (void)n_in; (void)out_size;
    const float* Phix   = (const float*)d_in[0];
    const float* Phi    = (const float*)d_in[1];
    const float* Qinit  = (const float*)d_in[2];
    const float* soft   = (const float*)d_in[3];
    const float* alphas = (const float*)d_in[4];
    const float* betas  = (const float*)d_in[5];
    const float* c1     = (const float*)d_in[6];
    const float* c2     = (const float*)d_in[7];
    const float* c3     = (const float*)d_in[8];
    const float* c4     = (const float*)d_in[9];
    float* out = (float*)d_out;

    cudaFuncSetAttribute(k_conv,   cudaFuncAttributeMaxDynamicSharedMemorySize, SMEM_CONV);
    cudaFuncSetAttribute(k_conv12, cudaFuncAttributeMaxDynamicSharedMemorySize, SMEM_C12);
    cudaFuncSetAttribute(k_convT1, cudaFuncAttributeMaxDynamicSharedMemorySize, SMEM_T1);

    float *px, *pz, *pgphi, *pdotm, *px1, *px2, *px3, *pg, *pbA, *pPhiTb;
    cudaGetSymbolAddress((void**)&px,     d_x);
    cudaGetSymbolAddress((void**)&pz,     d_z);
    cudaGetSymbolAddress((void**)&pgphi,  d_gphi);
    cudaGetSymbolAddress((void**)&pdotm,  d_dotm);
    cudaGetSymbolAddress((void**)&px1,    d_x1);
    cudaGetSymbolAddress((void**)&px2,    d_x2);
    cudaGetSymbolAddress((void**)&px3,    d_x3);
    cudaGetSymbolAddress((void**)&pg,     d_g);
    cudaGetSymbolAddress((void**)&pbA,    d_bA);
    cudaGetSymbolAddress((void**)&pPhiTb, d_PhiTb);

    dim3 tb16(16, 16);
    k_phitphi64<<<dim3(18, 18), tb16>>>(Phi);                       // + gamma init
    k_setupF<<<dim3(35, 8, 2), tb16>>>(Phix, Phi, Qinit, pPhiTb, px);

    for (int p = 0; p < 3; p++) {
        if (p == 0)
            k_gemmP<<<dim3(18, 4), tb16>>>(px, pz, alphas, p, 0);
        else
            k_zstep<<<BB, 256>>>(px, pz, alphas, p);
        grad_r_chain(pz, c1, c2, c3, c4, soft, px1, px2, px3, pg, pbA,
                     pz, px, pdotm, pgphi, alphas, betas, p, 0,
                     (p == 2) ? out : nullptr);
        if (p < 2) {
            k_gemmP<<<dim3(18, 4), tb16>>>(px, pdotm, alphas, p, 1);
            grad_r_chain(px, c1, c2, c3, c4, soft, px1, px2, px3, pg, pbA,
                         pz, px, pdotm, pgphi, alphas, betas, p, 1, nullptr);
            k_rownorm<<<BB, 256>>>(pgphi);
            k_gamma<<<1, 256>>>(soft);
        }
    }
}

// round 6
// speedup vs baseline: 1.2787x; 1.0162x over previous
#include <cuda_runtime.h>
#include <math.h>

#define BB   256
#define NPIX 1089
#define MDIM 272
#define CC   32
#define PADS 36
#define CH_STRIDE (35*PADS)   /* 1260 floats per padded channel */
#define CONV_THREADS 512
#define NITEM 792             /* 6 y-strips * 33 x * 4 channel-groups */

#define FLAG_ACT_IN 1
#define FLAG_FLIP   2
#define FLAG_ACTDER 4
#define FLAG_GNORM  8

typedef unsigned long long u64;

// ---------------- device state (static, no allocation) ----------------
__device__ float d_P[NPIX*NPIX];
__device__ float d_PhiTb[BB*NPIX];
__device__ float d_x[BB*NPIX];
__device__ float d_z[BB*NPIX];
__device__ float d_gphi[BB*NPIX];
__device__ float d_dotm[BB*NPIX];
__device__ float d_x1[BB*CC*NPIX];
__device__ float d_x2[BB*CC*NPIX];
__device__ float d_x3[BB*CC*NPIX];
__device__ float d_g [BB*CC*NPIX];
__device__ float d_bA[BB*CC*NPIX];
__device__ float d_ngrad[BB];
__device__ float d_gamma;

// ---------------- packed f32x2 helpers ----------------
__device__ __forceinline__ u64 pk2(float a, float b) {
    u64 r; asm("mov.b64 %0, {%1,%2};" : "=l"(r) : "f"(a), "f"(b)); return r;
}
__device__ __forceinline__ void fma2(u64& d, u64 a, u64 b) {
    asm("fma.rn.f32x2 %0, %1, %2, %3;" : "=l"(d) : "l"(a), "l"(b), "l"(d));
}
__device__ __forceinline__ float2 upk2(u64 v) {
    float2 f; asm("mov.b64 {%0,%1}, %2;" : "=f"(f.x), "=f"(f.y) : "l"(v)); return f;
}

// ---------------- activation (eq. 33), DELTA = 0.01 ----------------
__device__ __forceinline__ float actf(float v) {
    if (fabsf(v) > 0.01f) return fmaxf(v, 0.0f);
    return fmaf(v*v, 25.0f, fmaf(v, 0.5f, 0.0025f));
}
__device__ __forceinline__ float actdf(float v) {
    if (fabsf(v) > 0.01f) return v > 0.0f ? 1.0f : 0.0f;
    return fmaf(v, 50.0f, 0.5f);
}

// ---------------- GEMM: P = Phi^T Phi (64x64 tiles, 4x4 per thread) ----------------
__global__ void k_phitphi64(const float* __restrict__ Phi) {
    if (blockIdx.x == 0 && blockIdx.y == 0 && threadIdx.x == 0 && threadIdx.y == 0)
        d_gamma = 1.0f;
    __shared__ float As[16][68];
    __shared__ float Bs[16][68];
    int ib = blockIdx.y * 64, jb = blockIdx.x * 64;
    int tx = threadIdx.x, ty = threadIdx.y;
    int t = ty * 16 + tx;
    float acc[4][4];
    #pragma unroll
    for (int r = 0; r < 4; r++)
        #pragma unroll
        for (int c = 0; c < 4; c++) acc[r][c] = 0.f;

    for (int k0 = 0; k0 < MDIM; k0 += 16) {
        #pragma unroll
        for (int q = t; q < 1024; q += 256) {
            int kk = q / 64, r = q % 64;
            As[kk][r] = (ib + r < NPIX) ? Phi[(k0 + kk) * NPIX + ib + r] : 0.f;
            Bs[kk][r] = (jb + r < NPIX) ? Phi[(k0 + kk) * NPIX + jb + r] : 0.f;
        }
        __syncthreads();
        #pragma unroll
        for (int kk = 0; kk < 16; kk++) {
            float4 a4 = *(const float4*)&As[kk][ty * 4];
            float4 b4 = *(const float4*)&Bs[kk][tx * 4];
            float ar[4] = {a4.x, a4.y, a4.z, a4.w};
            float br[4] = {b4.x, b4.y, b4.z, b4.w};
            #pragma unroll
            for (int r = 0; r < 4; r++)
                #pragma unroll
                for (int c = 0; c < 4; c++)
                    acc[r][c] = fmaf(ar[r], br[c], acc[r][c]);
        }
        __syncthreads();
    }
    #pragma unroll
    for (int r = 0; r < 4; r++) {
        int i = ib + ty * 4 + r;
        if (i >= NPIX) continue;
        #pragma unroll
        for (int c = 0; c < 4; c++) {
            int j = jb + tx * 4 + c;
            if (j < NPIX) d_P[i * NPIX + j] = acc[r][c];
        }
    }
}

// ---------------- phase GEMM: dot = src @ P  (64x64, 4x4) ----------------
__global__ void k_gemmP(const float* __restrict__ src, float* __restrict__ dst,
                        const float* __restrict__ alphas, int phase, int mode) {
    __shared__ float As[16][68];
    __shared__ float Bs[16][68];
    int bb = blockIdx.y * 64, jb = blockIdx.x * 64;
    int tx = threadIdx.x, ty = threadIdx.y;
    int t = ty * 16 + tx;
    float acc[4][4];
    #pragma unroll
    for (int r = 0; r < 4; r++)
        #pragma unroll
        for (int c = 0; c < 4; c++) acc[r][c] = 0.f;

    for (int k0 = 0; k0 < NPIX; k0 += 16) {
        #pragma unroll
        for (int q = t; q < 1024; q += 256) {
            int r = q / 16, kk = q % 16;
            As[kk][r] = (k0 + kk < NPIX) ? src[(bb + r) * NPIX + k0 + kk] : 0.f;
        }
        #pragma unroll
        for (int q = t; q < 1024; q += 256) {
            int kk = q / 64, c = q % 64;
            Bs[kk][c] = (k0 + kk < NPIX && jb + c < NPIX) ? d_P[(k0 + kk) * NPIX + jb + c] : 0.f;
        }
        __syncthreads();
        #pragma unroll
        for (int kk = 0; kk < 16; kk++) {
            float4 a4 = *(const float4*)&As[kk][ty * 4];
            float4 b4 = *(const float4*)&Bs[kk][tx * 4];
            float ar[4] = {a4.x, a4.y, a4.z, a4.w};
            float br[4] = {b4.x, b4.y, b4.z, b4.w};
            #pragma unroll
            for (int r = 0; r < 4; r++)
                #pragma unroll
                for (int c = 0; c < 4; c++)
                    acc[r][c] = fmaf(ar[r], br[c], acc[r][c]);
        }
        __syncthreads();
    }
    float alpha = fabsf(alphas[phase]);
    #pragma unroll
    for (int r = 0; r < 4; r++) {
        int b = bb + ty * 4 + r;
        #pragma unroll
        for (int c = 0; c < 4; c++) {
            int j = jb + tx * 4 + c;
            if (j < NPIX) {
                float dot = acc[r][c];
                float ptb = d_PhiTb[b * NPIX + j];
                if (mode == 0)
                    dst[b * NPIX + j] = src[b * NPIX + j] + alpha * (ptb - dot);
                else
                    dst[b * NPIX + j] = dot - ptb;
            }
        }
    }
}

// ---------------- z step: z = x - |alpha|*dotm ----------------
__global__ void k_zstep(const float* __restrict__ x, float* __restrict__ z,
                        const float* __restrict__ alphas, int phase) {
    float alpha = fabsf(alphas[phase]);
    size_t base = (size_t)blockIdx.x * NPIX;
    for (int j = threadIdx.x; j < NPIX; j += blockDim.x)
        z[base + j] = x[base + j] - alpha * d_dotm[base + j];
}

// ---------------- fused setup GEMMs (blockIdx.z: 0 = PhiTb, 1 = x0) ----------------
__global__ void k_setupF(const float* __restrict__ Phix, const float* __restrict__ Phi,
                         const float* __restrict__ Qinit,
                         float* __restrict__ dPhiTb, float* __restrict__ dx) {
    __shared__ float As[32][33];
    __shared__ float Bs[32][33];
    int tmode = blockIdx.z;
    const float* Bsrc = tmode == 0 ? Phi : Qinit;
    float* dst = tmode == 0 ? dPhiTb : dx;
    int bb = blockIdx.y * 32, jb = blockIdx.x * 32;
    int tx = threadIdx.x, ty = threadIdx.y;
    int t = ty * 16 + tx;
    float acc00 = 0.f, acc01 = 0.f, acc10 = 0.f, acc11 = 0.f;
    for (int k0 = 0; k0 < MDIM; k0 += 32) {
        for (int q = t; q < 1024; q += 256) {
            int kk = q % 32, r = q / 32;
            As[kk][r] = (k0 + kk < MDIM) ? Phix[(bb + r) * MDIM + k0 + kk] : 0.f;
        }
        if (tmode == 0) {
            for (int q = t; q < 1024; q += 256) {
                int kk = q / 32, j = q % 32;
                Bs[kk][j] = (k0 + kk < MDIM && jb + j < NPIX) ? Bsrc[(k0 + kk) * NPIX + jb + j] : 0.f;
            }
        } else {
            for (int q = t; q < 1024; q += 256) {
                int kk = q % 32, j = q / 32;
                Bs[kk][j] = (k0 + kk < MDIM && jb + j < NPIX) ? Bsrc[(jb + j) * MDIM + k0 + kk] : 0.f;
            }
        }
        __syncthreads();
        #pragma unroll
        for (int kk = 0; kk < 32; kk++) {
            float a0 = As[kk][ty*2], a1 = As[kk][ty*2+1];
            float b0 = Bs[kk][tx*2], b1 = Bs[kk][tx*2+1];
            acc00 = fmaf(a0, b0, acc00); acc01 = fmaf(a0, b1, acc01);
            acc10 = fmaf(a1, b0, acc10); acc11 = fmaf(a1, b1, acc11);
        }
        __syncthreads();
    }
    int b0 = bb + ty*2, j0 = jb + tx*2;
    if (j0     < NPIX) dst[(b0  ) * NPIX + j0  ] = acc00;
    if (j0 + 1 < NPIX) dst[(b0  ) * NPIX + j0+1] = acc01;
    if (j0     < NPIX) dst[(b0+1) * NPIX + j0  ] = acc10;
    if (j0 + 1 < NPIX) dst[(b0+1) * NPIX + j0+1] = acc11;
}

// ---------------- heavy conv core: vertical 6-pixel strip x 8 output channels ----------
// Patch pre-packed to f32x2 (24 LDS + 24 pk2 per ci) feeding 216 FFMA2 (432 MAC).
__device__ __forceinline__ void conv_core6(const float* s_in, const float* s_w,
                                           float* __restrict__ outb,
                                           const float* __restrict__ preb,
                                           bool actder, int tid) {
    for (int it = tid; it < NITEM; it += CONV_THREADS) {
        int g  = it & 3;          // channel group (8 co)
        int q  = it >> 2;         // strip index
        int yq = q / 33;
        int x  = q - yq * 33;
        int y0 = yq * 6;
        int nval = 33 - y0; if (nval > 6) nval = 6;

        // acc[i][j]: pixel i (y0+i), co-pair j of group g
        u64 acc[6][4];
        #pragma unroll
        for (int i = 0; i < 6; i++)
            #pragma unroll
            for (int j = 0; j < 4; j++) acc[i][j] = 0ull;

        for (int ci = 0; ci < CC; ci++) {
            const float* sp = s_in + ci * CH_STRIDE;
            // patch rows: pixel-space y0-1 .. y0+6 => stored rows y0 .. y0+7 (clamp to 34)
            // pre-packed (v,v) to avoid per-tap pk2
            u64 patch[8][3];
            #pragma unroll
            for (int r = 0; r < 8; r++) {
                int sr = y0 + r; if (sr > 34) sr = 34;
                const float* rp = sp + sr * PADS + x;
                float v0 = rp[0], v1 = rp[1], v2 = rp[2];
                patch[r][0] = pk2(v0, v0);
                patch[r][1] = pk2(v1, v1);
                patch[r][2] = pk2(v2, v2);
            }
            const u64* wb = (const u64*)(s_w + ci * 9 * CC) + g * 4;
            #pragma unroll
            for (int ky = 0; ky < 3; ky++) {
                #pragma unroll
                for (int kx = 0; kx < 3; kx++) {
                    int k = ky * 3 + kx;
                    const ulonglong2* w2 = (const ulonglong2*)(wb + k * 16);
                    ulonglong2 wA = w2[0];   // co pair 0,1 of group (LDS.128)
                    ulonglong2 wB = w2[1];   // co pair 2,3 of group (LDS.128)
                    #pragma unroll
                    for (int i = 0; i < 6; i++) {
                        u64 vp = patch[i + ky][kx];
                        fma2(acc[i][0], vp, wA.x);
                        fma2(acc[i][1], vp, wA.y);
                        fma2(acc[i][2], vp, wB.x);
                        fma2(acc[i][3], vp, wB.y);
                    }
                }
            }
        }

        int cobase = g * 8;
        for (int i = 0; i < nval; i++) {
            int p = (y0 + i) * 33 + x;
            #pragma unroll
            for (int j = 0; j < 4; j++) {
                float2 a = upk2(acc[i][j]);
                int co0 = cobase + 2 * j;
                if (actder) {
                    a.x *= actdf(preb[co0 * NPIX + p]);
                    a.y *= actdf(preb[(co0 + 1) * NPIX + p]);
                }
                outb[co0 * NPIX + p]       = a.x;
                outb[(co0 + 1) * NPIX + p] = a.y;
            }
        }
    }
}

// stage weights into s_w with layout [ci][k][co] (optionally flipped/transposed)
__device__ __forceinline__ void stage_w(const float* __restrict__ w, float* s_w,
                                        bool flip, int tid) {
    for (int idx = tid; idx < CC * CC * 9; idx += CONV_THREADS) {
        int kx = idx % 3, ky = (idx / 3) % 3;
        int i = (idx / 9) % CC, o = idx / (9 * CC);
        float v = w[idx];
        int eci, eco, ek;
        if (flip) { eci = o; eco = i; ek = (2 - ky) * 3 + (2 - kx); }
        else      { eci = i; eco = o; ek = ky * 3 + kx; }
        s_w[(eci * 9 + ek) * CC + eco] = v;
    }
}

// ---------------- heavy 32->32 3x3 conv (fwd or transposed) ----------------
__global__ __launch_bounds__(CONV_THREADS, 1) void k_conv(
        const float* __restrict__ in, const float* __restrict__ w,
        float* __restrict__ out, const float* __restrict__ pre,
        const float* __restrict__ soft, int flags) {
    extern __shared__ float smem[];
    float* s_in = smem;                    // CC * CH_STRIDE
    float* s_w  = smem + CC * CH_STRIDE;   // [ci][k][co]
    int n = blockIdx.x, tid = threadIdx.x;

    for (int i = tid; i < CC * CH_STRIDE; i += CONV_THREADS) s_in[i] = 0.f;
    stage_w(w, s_w, (flags & FLAG_FLIP) != 0, tid);
    __syncthreads();

    const float* inb = in + (size_t)n * CC * NPIX;
    bool act_in = (flags & FLAG_ACT_IN) != 0;
    for (int idx = tid; idx < CC * NPIX; idx += CONV_THREADS) {
        int ci = idx / NPIX, p = idx - ci * NPIX;
        int y = p / 33, x = p - y * 33;
        float v = inb[idx];
        if (act_in) v = actf(v);
        s_in[ci * CH_STRIDE + (y + 1) * PADS + (x + 1)] = v;
    }
    __syncthreads();

    if (flags & FLAG_GNORM) {
        float thr = soft[0] * d_gamma;
        float inv_thr = 1.0f / thr;
        for (int p = tid; p < NPIX; p += CONV_THREADS) {
            int y = p / 33, x = p - y * 33;
            int off = (y + 1) * PADS + (x + 1);
            float v[CC];
            float s = 0.f;
            #pragma unroll
            for (int c = 0; c < CC; c++) {
                v[c] = s_in[c * CH_STRIDE + off];
                s = fmaf(v[c], v[c], s);
            }
            float nrm = sqrtf(s);
            float f = (nrm > thr) ? (1.0f / fmaxf(nrm, 1e-12f)) : inv_thr;
            #pragma unroll
            for (int c = 0; c < CC; c++) s_in[c * CH_STRIDE + off] = v[c] * f;
        }
        __syncthreads();
    }

    conv_core6(s_in, s_w,
               out + (size_t)n * CC * NPIX,
               pre + (size_t)n * CC * NPIX,
               (flags & FLAG_ACTDER) != 0, tid);
}

// ---------------- fused conv1 + conv2: z -> x1 (gmem) -> act -> conv2 -> x2 ----------
__global__ __launch_bounds__(CONV_THREADS, 1) void k_conv12(
        const float* __restrict__ z, const float* __restrict__ w1,
        const float* __restrict__ w2,
        float* __restrict__ x1out, float* __restrict__ x2out) {
    extern __shared__ float smem[];
    float* s_in = smem;                           // CC * CH_STRIDE (act(x1), padded)
    float* s_w  = s_in + CC * CH_STRIDE;          // CC*CC*9 (c2 weights)
    float* s_z  = s_w + CC * CC * 9;              // CH_STRIDE (padded z)
    float* s_w1 = s_z + CH_STRIDE;                // 9*CC  [k][co]
    int n = blockIdx.x, tid = threadIdx.x;

    for (int i = tid; i < CC * CH_STRIDE; i += CONV_THREADS) s_in[i] = 0.f;
    for (int i = tid; i < CH_STRIDE; i += CONV_THREADS) s_z[i] = 0.f;
    stage_w(w2, s_w, false, tid);
    for (int idx = tid; idx < CC * 9; idx += CONV_THREADS) {
        int o = idx / 9, k = idx % 9;
        s_w1[k * CC + o] = w1[idx];
    }
    __syncthreads();

    const float* zb = z + (size_t)n * NPIX;
    for (int p = tid; p < NPIX; p += CONV_THREADS) {
        int y = p / 33, x = p - y * 33;
        s_z[(y + 1) * PADS + (x + 1)] = zb[p];
    }
    __syncthreads();

    // conv1: thread per pixel, all 32 output channels
    float* x1b = x1out + (size_t)n * CC * NPIX;
    for (int p = tid; p < NPIX; p += CONV_THREADS) {
        int y = p / 33, x = p - y * 33;
        const float* sp = s_z + y * PADS + x;
        float zv[9];
        zv[0]=sp[0]; zv[1]=sp[1]; zv[2]=sp[2];
        zv[3]=sp[PADS]; zv[4]=sp[PADS+1]; zv[5]=sp[PADS+2];
        zv[6]=sp[2*PADS]; zv[7]=sp[2*PADS+1]; zv[8]=sp[2*PADS+2];
        float acc[CC];
        #pragma unroll
        for (int co = 0; co < CC; co++) acc[co] = 0.f;
        #pragma unroll
        for (int k = 0; k < 9; k++) {
            #pragma unroll
            for (int c4 = 0; c4 < 8; c4++) {
                float4 wv = *(const float4*)(s_w1 + k * CC + c4 * 4);
                acc[c4*4+0] = fmaf(zv[k], wv.x, acc[c4*4+0]);
                acc[c4*4+1] = fmaf(zv[k], wv.y, acc[c4*4+1]);
                acc[c4*4+2] = fmaf(zv[k], wv.z, acc[c4*4+2]);
                acc[c4*4+3] = fmaf(zv[k], wv.w, acc[c4*4+3]);
            }
        }
        int off = (y + 1) * PADS + (x + 1);
        #pragma unroll
        for (int co = 0; co < CC; co++) {
            x1b[co * NPIX + p] = acc[co];
            s_in[co * CH_STRIDE + off] = actf(acc[co]);
        }
    }
    __syncthreads();

    conv_core6(s_in, s_w, x2out + (size_t)n * CC * NPIX,
               x1out, false, tid);
}

// ---------------- convT1 (32 -> 1), fused with x/gphi update ----------------
__global__ __launch_bounds__(CONV_THREADS, 1) void k_convT1(
        const float* __restrict__ in, const float* __restrict__ w1,
        const float* __restrict__ z, float* __restrict__ x,
        const float* __restrict__ dotm, float* __restrict__ gphi,
        const float* __restrict__ alphas, const float* __restrict__ betas,
        int phase, int mode, float* __restrict__ out_extra) {
    extern __shared__ float smem[];
    float* s_in = smem;                 // CC * CH_STRIDE
    __shared__ float s_w[CC * 9];       // flipped [o][k]
    int n = blockIdx.x, tid = threadIdx.x;
    for (int i = tid; i < CC * CH_STRIDE; i += CONV_THREADS) s_in[i] = 0.f;
    for (int idx = tid; idx < CC * 9; idx += CONV_THREADS) {
        int o = idx / 9, k = idx % 9;
        int ky = k / 3, kx = k % 3;
        s_w[o * 9 + (2 - ky) * 3 + (2 - kx)] = w1[idx];
    }
    __syncthreads();
    const float* inb = in + (size_t)n * CC * NPIX;
    for (int idx = tid; idx < CC * NPIX; idx += CONV_THREADS) {
        int ci = idx / NPIX, p = idx - ci * NPIX;
        int y = p / 33, x2 = p - y * 33;
        s_in[ci * CH_STRIDE + (y + 1) * PADS + (x2 + 1)] = inb[idx];
    }
    __syncthreads();

    float a = fabsf(alphas[phase]), b = fabsf(betas[phase]);
    float tau = a * b / (a + b);

    for (int p = tid; p < NPIX; p += CONV_THREADS) {
        int y = p / 33, xx = p - y * 33;
        float acc = 0.f;
        const float* sbase = s_in + y * PADS + xx;
        for (int o = 0; o < CC; o++) {
            const float* sp = sbase + o * CH_STRIDE;
            const float* wp = s_w + o * 9;
            #pragma unroll
            for (int k = 0; k < 9; k++)
                acc = fmaf(sp[(k / 3) * PADS + (k % 3)], wp[k], acc);
        }
        size_t off = (size_t)n * NPIX + p;
        if (mode == 0) {
            float nx = z[off] - tau * acc;
            x[off] = nx;
            if (out_extra) out_extra[off] = nx;
        } else {
            gphi[off] = dotm[off] + acc;
        }
    }
}

// ---------------- row norms + gamma update ----------------
__global__ void k_rownorm(const float* __restrict__ gphi) {
    __shared__ float red[256];
    int bidx = blockIdx.x;
    float s = 0.f;
    for (int j = threadIdx.x; j < NPIX; j += 256) {
        float v = gphi[(size_t)bidx * NPIX + j];
        s = fmaf(v, v, s);
    }
    red[threadIdx.x] = s;
    __syncthreads();
    for (int off = 128; off > 0; off >>= 1) {
        if (threadIdx.x < off) red[threadIdx.x] += red[threadIdx.x + off];
        __syncthreads();
    }
    if (threadIdx.x == 0) d_ngrad[bidx] = sqrtf(red[0]);
}

__global__ void k_gamma(const float* __restrict__ soft_thr) {
    __shared__ float red[256];
    red[threadIdx.x] = d_ngrad[threadIdx.x];
    __syncthreads();
    for (int off = 128; off > 0; off >>= 1) {
        if (threadIdx.x < off) red[threadIdx.x] += red[threadIdx.x + off];
        __syncthreads();
    }
    if (threadIdx.x == 0) {
        float mean = red[0] / (float)BB;
        float g = d_gamma;
        if (mean < 15000.0f * g * soft_thr[0]) g *= 0.9f;
        d_gamma = g;
    }
}

// ---------------- host orchestration ----------------
#define SMEM_CONV ((CC * CH_STRIDE + CC * CC * 9) * (int)sizeof(float))              /* 198144 */
#define SMEM_C12  ((CC * CH_STRIDE + CC * CC * 9 + CH_STRIDE + 9 * CC) * (int)sizeof(float)) /* 204336 */
#define SMEM_T1   ((CC * CH_STRIDE) * (int)sizeof(float))                            /* 161280 */

static void grad_r_chain(const float* src, const float* c1, const float* c2,
                         const float* c3, const float* c4, const float* soft,
                         float* px1, float* px2, float* px3, float* pg, float* pbA,
                         const float* pz, float* px, const float* pdotm, float* pgphi,
                         const float* alphas, const float* betas,
                         int phase, int mode, float* out_extra) {
    k_conv12<<<BB, CONV_THREADS, SMEM_C12>>>(src, c1, c2, px1, px2);
    k_conv<<<BB, CONV_THREADS, SMEM_CONV>>>(px2, c3, px3, px1, soft, FLAG_ACT_IN);
    k_conv<<<BB, CONV_THREADS, SMEM_CONV>>>(px3, c4, pg,  px1, soft, FLAG_ACT_IN);
    k_conv<<<BB, CONV_THREADS, SMEM_CONV>>>(pg,  c4, pbA, px3, soft, FLAG_FLIP | FLAG_ACTDER | FLAG_GNORM);
    k_conv<<<BB, CONV_THREADS, SMEM_CONV>>>(pbA, c3, pg,  px2, soft, FLAG_FLIP | FLAG_ACTDER);
    k_conv<<<BB, CONV_THREADS, SMEM_CONV>>>(pg,  c2, pbA, px1, soft, FLAG_FLIP | FLAG_ACTDER);
    k_convT1<<<BB, CONV_THREADS, SMEM_T1>>>(pbA, c1, pz, px, pdotm, pgphi,
                                            alphas, betas, phase, mode, out_extra);
}

extern "C" void kernel_launch(void* const* d_in, const int* in_sizes, int n_in,
                              void* d_out, int out_size) {
    (void)in_sizes; (void)n_in; (void)out_size;
    const float* Phix   = (const float*)d_in[0];
    const float* Phi    = (const float*)d_in[1];
    const float* Qinit  = (const float*)d_in[2];
    const float* soft   = (const float*)d_in[3];
    const float* alphas = (const float*)d_in[4];
    const float* betas  = (const float*)d_in[5];
    const float* c1     = (const float*)d_in[6];
    const float* c2     = (const float*)d_in[7];
    const float* c3     = (const float*)d_in[8];
    const float* c4     = (const float*)d_in[9];
    float* out = (float*)d_out;

    cudaFuncSetAttribute(k_conv,   cudaFuncAttributeMaxDynamicSharedMemorySize, SMEM_CONV);
    cudaFuncSetAttribute(k_conv12, cudaFuncAttributeMaxDynamicSharedMemorySize, SMEM_C12);
    cudaFuncSetAttribute(k_convT1, cudaFuncAttributeMaxDynamicSharedMemorySize, SMEM_T1);

    float *px, *pz, *pgphi, *pdotm, *px1, *px2, *px3, *pg, *pbA, *pPhiTb;
    cudaGetSymbolAddress((void**)&px,     d_x);
    cudaGetSymbolAddress((void**)&pz,     d_z);
    cudaGetSymbolAddress((void**)&pgphi,  d_gphi);
    cudaGetSymbolAddress((void**)&pdotm,  d_dotm);
    cudaGetSymbolAddress((void**)&px1,    d_x1);
    cudaGetSymbolAddress((void**)&px2,    d_x2);
    cudaGetSymbolAddress((void**)&px3,    d_x3);
    cudaGetSymbolAddress((void**)&pg,     d_g);
    cudaGetSymbolAddress((void**)&pbA,    d_bA);
    cudaGetSymbolAddress((void**)&pPhiTb, d_PhiTb);

    dim3 tb16(16, 16);
    k_phitphi64<<<dim3(18, 18), tb16>>>(Phi);                       // + gamma init
    k_setupF<<<dim3(35, 8, 2), tb16>>>(Phix, Phi, Qinit, pPhiTb, px);

    for (int p = 0; p < 3; p++) {
        if (p == 0)
            k_gemmP<<<dim3(18, 4), tb16>>>(px, pz, alphas, p, 0);
        else
            k_zstep<<<BB, 256>>>(px, pz, alphas, p);
        grad_r_chain(pz, c1, c2, c3, c4, soft, px1, px2, px3, pg, pbA,
                     pz, px, pdotm, pgphi, alphas, betas, p, 0,
                     (p == 2) ? out : nullptr);
        if (p < 2) {
            k_gemmP<<<dim3(18, 4), tb16>>>(px, pdotm, alphas, p, 1);
            grad_r_chain(px, c1, c2, c3, c4, soft, px1, px2, px3, pg, pbA,
                         pz, px, pdotm, pgphi, alphas, betas, p, 1, nullptr);
            k_rownorm<<<BB, 256>>>(pgphi);
            k_gamma<<<1, 256>>>(soft);
        }
    }
}